// round 9
// baseline (speedup 1.0000x reference)
#include <cuda_runtime.h>
#include <cuda_bf16.h>
#include <cstdint>

// Problem constants (fixed by the dataset)
#define NN   50000
#define EE   800000
#define C    128
#define COUT 64
#define EPSV 1e-5f
#define APITCH 132

// ---------------- device scratch (no allocations allowed) ----------------
// Invariant: g_cnt and g_deg are ZERO at the start of every kernel_launch call.
// (zero at module load; head_kernel re-zeroes both at the end of each call.)
__device__ float g_deg[NN];
__device__ int   g_cnt[NN];
__device__ int   g_rowstart[NN + 1];
__device__ int   g_cursor[NN];
__device__ int2  g_cw[EE];             // interleaved pairs: (col, wv-bits)
__device__ float g_agg[(size_t)NN * C];
__device__ float g_bufA[(size_t)NN * C];
__device__ float g_bufB[(size_t)NN * C];
__device__ float g_bnA[3 * C];
__device__ float g_bnB[3 * C];
__device__ float g_wt[5 * 128 * 128];  // transposed weights WT[n][k], tf32-rounded

__device__ __forceinline__ float to_tf32(float f) {
    uint32_t u;
    asm("cvt.rna.tf32.f32 %0, %1;" : "=r"(u) : "f"(f));
    return __uint_as_float(u);
}

__device__ __forceinline__ void mma8(float* d, const uint32_t* a, const uint32_t* b) {
    asm volatile(
        "mma.sync.aligned.m16n8k8.row.col.f32.tf32.tf32.f32 "
        "{%0,%1,%2,%3}, {%4,%5,%6,%7}, {%8,%9}, {%0,%1,%2,%3};"
        : "+f"(d[0]), "+f"(d[1]), "+f"(d[2]), "+f"(d[3])
        : "r"(a[0]), "r"(a[1]), "r"(a[2]), "r"(a[3]), "r"(b[0]), "r"(b[1]));
}

// ---------------- kernel 0: edge count/degree atomics + weight transpose ----------------
__global__ void count_tr_kernel(const int* __restrict__ dst, const float* __restrict__ ew, int e,
                                const float* __restrict__ w1, const float* __restrict__ conv_ws,
                                const float* __restrict__ lin1_w, const float* __restrict__ lin2_w) {
    int nb_e = (e + 255) / 256;
    if ((int)blockIdx.x < nb_e) {
        int i = blockIdx.x * 256 + threadIdx.x;
        if (i < e) {
            int d = dst[i];
            atomicAdd(&g_cnt[d], 1);
            atomicAdd(&g_deg[d], ew[i]);
        }
        return;
    }
    int g = (blockIdx.x - nb_e) * 256 + threadIdx.x;
    if (g < 4 * 16384) {
        int mat = g >> 14, idx = g & 16383;
        int k = idx >> 7, nn = idx & 127;
        const float* W = (mat == 0) ? w1 : ((mat == 3) ? lin1_w : (conv_ws + (mat - 1) * 16384));
        g_wt[mat * 16384 + nn * 128 + k] = to_tf32(W[k * 128 + nn]);
    } else if (g < 4 * 16384 + 8192) {
        int idx = g - 4 * 16384;
        int k = idx >> 6, nn = idx & 63;
        g_wt[4 * 16384 + nn * 128 + k] = to_tf32(lin2_w[k * 64 + nn]);
    }
}

// ---------------- kernel 1: single-block scan + dis + cursor + BN fold ----------------
__global__ void scan_fused_kernel(int n, const float* b1,
                                  const float* g1, const float* be1, const float* m1, const float* v1,
                                  const float* conv_bs,
                                  const float* gs, const float* bes, const float* ms, const float* vs) {
    __shared__ int wsum[32];
    __shared__ int carry;
    int t = threadIdx.x, lane = t & 31, w = t >> 5;
    if (t == 0) carry = 0;
    __syncthreads();
    for (int base = 0; base < n; base += 1024) {
        int i = base + t;
        int v = (i < n) ? g_cnt[i] : 0;
        int x = v;
        #pragma unroll
        for (int o = 1; o < 32; o <<= 1) { int y = __shfl_up_sync(0xffffffffu, x, o); if (lane >= o) x += y; }
        if (lane == 31) wsum[w] = x;
        __syncthreads();
        if (w == 0) {
            int s = wsum[lane];
            #pragma unroll
            for (int o = 1; o < 32; o <<= 1) { int y = __shfl_up_sync(0xffffffffu, s, o); if (lane >= o) s += y; }
            wsum[lane] = s;
        }
        __syncthreads();
        int incl = x + (w > 0 ? wsum[w - 1] : 0) + carry;
        if (i < n) g_rowstart[i] = incl - v;
        __syncthreads();
        if (t == 1023) carry = incl;
        __syncthreads();
    }
    if (t == 0) g_rowstart[n] = carry;
    __syncthreads();
    for (int i = t; i < n; i += 1024) {
        g_deg[i] = rsqrtf(g_deg[i] + 1.0f);   // + self loop
        g_cursor[i] = g_rowstart[i];
    }
    if (t < C) {
        int c = t;
        float sc = g1[c] * rsqrtf(v1[c] + EPSV);
        g_bnA[c] = sc;
        g_bnB[c] = be1[c] + (b1[c] - m1[c]) * sc;
        #pragma unroll
        for (int l = 0; l < 2; l++) {
            float s2 = gs[l * C + c] * rsqrtf(vs[l * C + c] + EPSV);
            g_bnA[(1 + l) * C + c] = s2;
            g_bnB[(1 + l) * C + c] = bes[l * C + c] + (conv_bs[l * C + c] - ms[l * C + c]) * s2;
        }
    }
}

// ---------------- kernel 2: CSR fill (interleaved pairs, single 8B store) ----------------
__global__ void fill_kernel(const int* __restrict__ src, const int* __restrict__ dst,
                            const float* __restrict__ ew, int e) {
    int i = blockIdx.x * blockDim.x + threadIdx.x;
    if (i < e) {
        int s = src[i], d = dst[i];
        int pos = atomicAdd(&g_cursor[d], 1);
        float w = g_deg[s] * ew[i] * g_deg[d];
        g_cw[pos] = make_int2(s, __float_as_int(w));
    }
}

// ---------------- aggregation: g_agg[i] = selfnorm*H[i] + sum_e w_e * H[col_e] ----------------
// warp-per-row. Per 8 edges: ONE coalesced LDG.64 (lanes 0-7 hold the pairs) +
// shfl broadcasts -> ~1/3 fewer L1tex wavefronts than broadcast-load versions,
// and only one int2 live -> low regs, high occupancy.
__global__ __launch_bounds__(256) void agg_kernel(const float* __restrict__ H, int n) {
    int wid = threadIdx.x >> 5, lane = threadIdx.x & 31;
    int m = blockIdx.x * 8 + wid;
    if (m >= n) return;
    int l8 = lane & 7;

    const float* Hl = H + lane * 4;
    float dis = g_deg[m];
    float w0 = dis * dis;
    float4 h4 = *reinterpret_cast<const float4*>(&Hl[(size_t)m * 128]);
    float4 acc = make_float4(w0 * h4.x, w0 * h4.y, w0 * h4.z, w0 * h4.w);

    int s = g_rowstart[m], e = g_rowstart[m + 1];
    int kfull = s + ((e - s) & ~7);
    int k = s;
    for (; k < kfull; k += 8) {
        int2 p = __ldg(&g_cw[k + l8]);
        int   c0 = __shfl_sync(0xffffffffu, p.x, 0, 8);
        int   c1 = __shfl_sync(0xffffffffu, p.x, 1, 8);
        int   c2 = __shfl_sync(0xffffffffu, p.x, 2, 8);
        int   c3 = __shfl_sync(0xffffffffu, p.x, 3, 8);
        int   c4 = __shfl_sync(0xffffffffu, p.x, 4, 8);
        int   c5 = __shfl_sync(0xffffffffu, p.x, 5, 8);
        int   c6 = __shfl_sync(0xffffffffu, p.x, 6, 8);
        int   c7 = __shfl_sync(0xffffffffu, p.x, 7, 8);
        float w0e = __int_as_float(__shfl_sync(0xffffffffu, p.y, 0, 8));
        float w1e = __int_as_float(__shfl_sync(0xffffffffu, p.y, 1, 8));
        float w2e = __int_as_float(__shfl_sync(0xffffffffu, p.y, 2, 8));
        float w3e = __int_as_float(__shfl_sync(0xffffffffu, p.y, 3, 8));
        float w4e = __int_as_float(__shfl_sync(0xffffffffu, p.y, 4, 8));
        float w5e = __int_as_float(__shfl_sync(0xffffffffu, p.y, 5, 8));
        float w6e = __int_as_float(__shfl_sync(0xffffffffu, p.y, 6, 8));
        float w7e = __int_as_float(__shfl_sync(0xffffffffu, p.y, 7, 8));
        float4 v0 = *reinterpret_cast<const float4*>(&Hl[(size_t)c0 * 128]);
        float4 v1 = *reinterpret_cast<const float4*>(&Hl[(size_t)c1 * 128]);
        float4 v2 = *reinterpret_cast<const float4*>(&Hl[(size_t)c2 * 128]);
        float4 v3 = *reinterpret_cast<const float4*>(&Hl[(size_t)c3 * 128]);
        float4 v4 = *reinterpret_cast<const float4*>(&Hl[(size_t)c4 * 128]);
        float4 v5 = *reinterpret_cast<const float4*>(&Hl[(size_t)c5 * 128]);
        float4 v6 = *reinterpret_cast<const float4*>(&Hl[(size_t)c6 * 128]);
        float4 v7 = *reinterpret_cast<const float4*>(&Hl[(size_t)c7 * 128]);
        acc.x += w0e * v0.x + w1e * v1.x + w2e * v2.x + w3e * v3.x
               + w4e * v4.x + w5e * v5.x + w6e * v6.x + w7e * v7.x;
        acc.y += w0e * v0.y + w1e * v1.y + w2e * v2.y + w3e * v3.y
               + w4e * v4.y + w5e * v5.y + w6e * v6.y + w7e * v7.y;
        acc.z += w0e * v0.z + w1e * v1.z + w2e * v2.z + w3e * v3.z
               + w4e * v4.z + w5e * v5.z + w6e * v6.z + w7e * v7.z;
        acc.w += w0e * v0.w + w1e * v1.w + w2e * v2.w + w3e * v3.w
               + w4e * v4.w + w5e * v5.w + w6e * v6.w + w7e * v7.w;
    }
    int rem = e - k;   // 0..7
    if (rem > 0) {
        int2 p = __ldg(&g_cw[k + (l8 < rem ? l8 : rem - 1)]);
        #pragma unroll
        for (int j = 0; j < 7; j++) {
            if (j < rem) {
                int   c = __shfl_sync(0xffffffffu, p.x, j, 8);
                float wj = __int_as_float(__shfl_sync(0xffffffffu, p.y, j, 8));
                float4 v = *reinterpret_cast<const float4*>(&Hl[(size_t)c * 128]);
                acc.x += wj * v.x; acc.y += wj * v.y;
                acc.z += wj * v.z; acc.w += wj * v.w;
            }
        }
    }
    *reinterpret_cast<float4*>(&g_agg[(size_t)m * 128 + lane * 4]) = acc;
}

// ---------------- GEMM + BN + residual + lrelu (full-K, R5 layout) ----------------
template <int HASRES>
__global__ __launch_bounds__(256) void gemm_bn_kernel(const float* __restrict__ WT,
                                                      int layer, const float* __restrict__ H,
                                                      float* __restrict__ out, int M) {
    extern __shared__ float sm[];
    float* As = sm;                    // [128][APITCH]
    float* Ws = sm + 128 * APITCH;     // [128][APITCH]

    int tid = threadIdx.x;
    int wid = tid >> 5, lane = tid & 31;
    int m0 = blockIdx.x * 128;

    #pragma unroll
    for (int it = 0; it < 16; it++) {
        int idx = tid + it * 256;
        int r = idx >> 5, q = idx & 31;
        int m = m0 + r;
        float4 v = make_float4(0.f, 0.f, 0.f, 0.f);
        if (m < M) v = *reinterpret_cast<const float4*>(&g_agg[(size_t)m * 128 + q * 4]);
        float* p = &As[r * APITCH + q * 4];
        p[0] = to_tf32(v.x); p[1] = to_tf32(v.y); p[2] = to_tf32(v.z); p[3] = to_tf32(v.w);
    }
    #pragma unroll
    for (int it = 0; it < 16; it++) {
        int idx = tid + it * 256;
        int r = idx >> 5, q = idx & 31;
        float4 v = *reinterpret_cast<const float4*>(&WT[(size_t)r * 128 + q * 4]);
        *reinterpret_cast<float4*>(&Ws[r * APITCH + q * 4]) = v;
    }
    __syncthreads();

    int wm = wid & 3, wn = wid >> 2;
    int grp = lane >> 2, tg = lane & 3;
    int arow = wm * 32 + grp;
    int brow = wn * 64 + grp;

    float d[2][8][4];
    #pragma unroll
    for (int i = 0; i < 2; i++)
        #pragma unroll
        for (int j = 0; j < 8; j++)
            #pragma unroll
            for (int q = 0; q < 4; q++) d[i][j][q] = 0.0f;

    #pragma unroll
    for (int k0 = 0; k0 < 16; k0++) {
        int kk = k0 * 8 + tg;
        uint32_t a[2][4];
        #pragma unroll
        for (int mf = 0; mf < 2; mf++) {
            const float* ap = &As[(arow + mf * 16) * APITCH + kk];
            a[mf][0] = __float_as_uint(ap[0]);
            a[mf][2] = __float_as_uint(ap[4]);
            a[mf][1] = __float_as_uint(ap[8 * APITCH]);
            a[mf][3] = __float_as_uint(ap[8 * APITCH + 4]);
        }
        uint32_t b[8][2];
        #pragma unroll
        for (int nf = 0; nf < 8; nf++) {
            const float* bp = &Ws[(brow + nf * 8) * APITCH + kk];
            b[nf][0] = __float_as_uint(bp[0]);
            b[nf][1] = __float_as_uint(bp[4]);
        }
        #pragma unroll
        for (int mf = 0; mf < 2; mf++)
            #pragma unroll
            for (int nf = 0; nf < 8; nf++)
                mma8(d[mf][nf], a[mf], b[nf]);
    }

    const float* bnA = &g_bnA[layer * C];
    const float* bnB = &g_bnB[layer * C];
    #pragma unroll
    for (int mf = 0; mf < 2; mf++) {
        #pragma unroll
        for (int half = 0; half < 2; half++) {
            int m = m0 + wm * 32 + mf * 16 + half * 8 + grp;
            if (m < M) {
                #pragma unroll
                for (int nf = 0; nf < 8; nf++) {
                    int ncol = wn * 64 + nf * 8 + tg * 2;
                    float2 v;
                    v.x = d[mf][nf][half * 2 + 0] * bnA[ncol]     + bnB[ncol];
                    v.y = d[mf][nf][half * 2 + 1] * bnA[ncol + 1] + bnB[ncol + 1];
                    if (HASRES) {
                        float2 rv = *reinterpret_cast<const float2*>(&H[(size_t)m * 128 + ncol]);
                        v.x += rv.x; v.y += rv.y;
                    }
                    v.x = v.x > 0.f ? v.x : 0.01f * v.x;
                    v.y = v.y > 0.f ? v.y : 0.01f * v.y;
                    *reinterpret_cast<float2*>(&out[(size_t)m * 128 + ncol]) = v;
                }
            }
        }
    }
}

// ---------------- fused head + invariant restore (g_cnt, g_deg -> 0) ----------------
__global__ __launch_bounds__(256) void head_kernel(const float* __restrict__ H,
                                                   const float* __restrict__ WT1,
                                                   const float* __restrict__ bias1,
                                                   const float* __restrict__ WT2,
                                                   const float* __restrict__ bias2,
                                                   float* __restrict__ out, int M) {
    extern __shared__ float sm[];
    float* As  = sm;                          // [128][APITCH]
    float* W1s = sm + 128 * APITCH;           // [128][APITCH]
    float* W2s = sm + 256 * APITCH;           // [64][APITCH]

    int tid = threadIdx.x;
    int wid = tid >> 5, lane = tid & 31;
    int m0 = blockIdx.x * 128;

    // restore zero invariant (head runs after last use of g_deg / g_cnt)
    {
        int z = blockIdx.x * 256 + tid;
        if (z < NN) { g_deg[z] = 0.0f; g_cnt[z] = 0; }
    }

    #pragma unroll
    for (int it = 0; it < 16; it++) {
        int idx = tid + it * 256;
        int r = idx >> 5, q = idx & 31;
        int m = m0 + r;
        float4 v = make_float4(0.f, 0.f, 0.f, 0.f);
        if (m < M) v = *reinterpret_cast<const float4*>(&H[(size_t)m * 128 + q * 4]);
        float* p = &As[r * APITCH + q * 4];
        p[0] = to_tf32(v.x); p[1] = to_tf32(v.y); p[2] = to_tf32(v.z); p[3] = to_tf32(v.w);
    }
    #pragma unroll
    for (int it = 0; it < 16; it++) {
        int idx = tid + it * 256;
        int r = idx >> 5, q = idx & 31;
        float4 v = *reinterpret_cast<const float4*>(&WT1[(size_t)r * 128 + q * 4]);
        *reinterpret_cast<float4*>(&W1s[r * APITCH + q * 4]) = v;
    }
    #pragma unroll
    for (int it = 0; it < 8; it++) {
        int idx = tid + it * 256;
        int r = idx >> 5, q = idx & 31;
        float4 v = *reinterpret_cast<const float4*>(&WT2[(size_t)r * 128 + q * 4]);
        *reinterpret_cast<float4*>(&W2s[r * APITCH + q * 4]) = v;
    }
    __syncthreads();

    int wm = wid & 3, wn = wid >> 2;
    int grp = lane >> 2, tg = lane & 3;
    int arow = wm * 32 + grp;

    // ---- MMA1: z = H @ lin1 ----
    {
        int brow = wn * 64 + grp;
        float d[2][8][4];
        #pragma unroll
        for (int i = 0; i < 2; i++)
            #pragma unroll
            for (int j = 0; j < 8; j++)
                #pragma unroll
                for (int q = 0; q < 4; q++) d[i][j][q] = 0.0f;

        #pragma unroll
        for (int k0 = 0; k0 < 16; k0++) {
            int kk = k0 * 8 + tg;
            uint32_t a[2][4];
            #pragma unroll
            for (int mf = 0; mf < 2; mf++) {
                const float* ap = &As[(arow + mf * 16) * APITCH + kk];
                a[mf][0] = __float_as_uint(ap[0]);
                a[mf][2] = __float_as_uint(ap[4]);
                a[mf][1] = __float_as_uint(ap[8 * APITCH]);
                a[mf][3] = __float_as_uint(ap[8 * APITCH + 4]);
            }
            uint32_t b[8][2];
            #pragma unroll
            for (int nf = 0; nf < 8; nf++) {
                const float* bp = &W1s[(brow + nf * 8) * APITCH + kk];
                b[nf][0] = __float_as_uint(bp[0]);
                b[nf][1] = __float_as_uint(bp[4]);
            }
            #pragma unroll
            for (int mf = 0; mf < 2; mf++)
                #pragma unroll
                for (int nf = 0; nf < 8; nf++)
                    mma8(d[mf][nf], a[mf], b[nf]);
        }
        __syncthreads();

        #pragma unroll
        for (int mf = 0; mf < 2; mf++) {
            #pragma unroll
            for (int half = 0; half < 2; half++) {
                int r = wm * 32 + mf * 16 + half * 8 + grp;
                #pragma unroll
                for (int nf = 0; nf < 8; nf++) {
                    int ncol = wn * 64 + nf * 8 + tg * 2;
                    float vx = d[mf][nf][half * 2 + 0] + bias1[ncol];
                    float vy = d[mf][nf][half * 2 + 1] + bias1[ncol + 1];
                    vx = vx > 0.f ? vx : 0.01f * vx;
                    vy = vy > 0.f ? vy : 0.01f * vy;
                    As[r * APITCH + ncol]     = to_tf32(vx);
                    As[r * APITCH + ncol + 1] = to_tf32(vy);
                }
            }
        }
        __syncthreads();
    }

    // ---- MMA2: out = z @ lin2 ----
    {
        int brow = wn * 32 + grp;
        float d[2][4][4];
        #pragma unroll
        for (int i = 0; i < 2; i++)
            #pragma unroll
            for (int j = 0; j < 4; j++)
                #pragma unroll
                for (int q = 0; q < 4; q++) d[i][j][q] = 0.0f;

        #pragma unroll
        for (int k0 = 0; k0 < 16; k0++) {
            int kk = k0 * 8 + tg;
            uint32_t a[2][4];
            #pragma unroll
            for (int mf = 0; mf < 2; mf++) {
                const float* ap = &As[(arow + mf * 16) * APITCH + kk];
                a[mf][0] = __float_as_uint(ap[0]);
                a[mf][2] = __float_as_uint(ap[4]);
                a[mf][1] = __float_as_uint(ap[8 * APITCH]);
                a[mf][3] = __float_as_uint(ap[8 * APITCH + 4]);
            }
            uint32_t b[4][2];
            #pragma unroll
            for (int nf = 0; nf < 4; nf++) {
                const float* bp = &W2s[(brow + nf * 8) * APITCH + kk];
                b[nf][0] = __float_as_uint(bp[0]);
                b[nf][1] = __float_as_uint(bp[4]);
            }
            #pragma unroll
            for (int mf = 0; mf < 2; mf++)
                #pragma unroll
                for (int nf = 0; nf < 4; nf++)
                    mma8(d[mf][nf], a[mf], b[nf]);
        }

        #pragma unroll
        for (int mf = 0; mf < 2; mf++) {
            #pragma unroll
            for (int half = 0; half < 2; half++) {
                int m = m0 + wm * 32 + mf * 16 + half * 8 + grp;
                if (m < M) {
                    #pragma unroll
                    for (int nf = 0; nf < 4; nf++) {
                        int ncol = wn * 32 + nf * 8 + tg * 2;
                        float2 v;
                        v.x = d[mf][nf][half * 2 + 0] + bias2[ncol];
                        v.y = d[mf][nf][half * 2 + 1] + bias2[ncol + 1];
                        *reinterpret_cast<float2*>(&out[(size_t)m * COUT + ncol]) = v;
                    }
                }
            }
        }
    }
}

// ---------------- launch ----------------
extern "C" void kernel_launch(void* const* d_in, const int* in_sizes, int n_in,
                              void* d_out, int out_size) {
    const float* x       = (const float*)d_in[0];
    const int*   ei      = (const int*)d_in[1];
    const float* ew      = (const float*)d_in[2];
    const float* w1      = (const float*)d_in[3];
    const float* b1      = (const float*)d_in[4];
    const float* bn1_g   = (const float*)d_in[5];
    const float* bn1_b   = (const float*)d_in[6];
    const float* bn1_m   = (const float*)d_in[7];
    const float* bn1_v   = (const float*)d_in[8];
    const float* conv_ws = (const float*)d_in[9];
    const float* conv_bs = (const float*)d_in[10];
    const float* bns_g   = (const float*)d_in[11];
    const float* bns_b   = (const float*)d_in[12];
    const float* bns_m   = (const float*)d_in[13];
    const float* bns_v   = (const float*)d_in[14];
    const float* lin1_w  = (const float*)d_in[15];
    const float* lin1_b  = (const float*)d_in[16];
    const float* lin2_w  = (const float*)d_in[17];
    const float* lin2_b  = (const float*)d_in[18];

    int n = in_sizes[0] / C;     // 50000
    int e = in_sizes[2];         // 800000
    const int* srcp = ei;
    const int* dstp = ei + e;

    const int SMEM_GEMM = 256 * APITCH * 4;   // 135168
    const int SMEM_HEAD = 320 * APITCH * 4;   // 168960

    cudaFuncSetAttribute(gemm_bn_kernel<0>, cudaFuncAttributeMaxDynamicSharedMemorySize, SMEM_GEMM);
    cudaFuncSetAttribute(gemm_bn_kernel<1>, cudaFuncAttributeMaxDynamicSharedMemorySize, SMEM_GEMM);
    cudaFuncSetAttribute(head_kernel,       cudaFuncAttributeMaxDynamicSharedMemorySize, SMEM_HEAD);

    float* wt = nullptr;   cudaGetSymbolAddress((void**)&wt, g_wt);
    float* bufA = nullptr; cudaGetSymbolAddress((void**)&bufA, g_bufA);
    float* bufB = nullptr; cudaGetSymbolAddress((void**)&bufB, g_bufB);

    int nb_e = (e + 255) / 256;
    count_tr_kernel<<<nb_e + (5 * 16384 - 8192 + 255) / 256, 256>>>(dstp, ew, e, w1, conv_ws, lin1_w, lin2_w);
    scan_fused_kernel<<<1, 1024>>>(n, b1, bn1_g, bn1_b, bn1_m, bn1_v,
                                   conv_bs, bns_g, bns_b, bns_m, bns_v);
    fill_kernel<<<nb_e, 256>>>(srcp, dstp, ew, e);

    int ablocks = (n + 7) / 8;
    int gblocks = (n + 127) / 128;

    // layer 0                                  <- agg at ncu capture slot
    agg_kernel<<<ablocks, 256>>>(x, n);
    gemm_bn_kernel<0><<<gblocks, 256, SMEM_GEMM>>>(wt + 0 * 16384, 0, nullptr, bufA, n);

    // layer 1
    agg_kernel<<<ablocks, 256>>>(bufA, n);
    gemm_bn_kernel<1><<<gblocks, 256, SMEM_GEMM>>>(wt + 1 * 16384, 1, bufA, bufB, n);

    // layer 2
    agg_kernel<<<ablocks, 256>>>(bufB, n);
    gemm_bn_kernel<1><<<gblocks, 256, SMEM_GEMM>>>(wt + 2 * 16384, 2, bufB, bufA, n);

    // fused heads (also restores g_cnt/g_deg = 0)
    head_kernel<<<gblocks, 256, SMEM_HEAD>>>(bufA, wt + 3 * 16384, lin1_b, wt + 4 * 16384, lin2_b,
                                             (float*)d_out, n);
}

// round 10
// speedup vs baseline: 1.3318x; 1.3318x over previous
#include <cuda_runtime.h>
#include <cuda_bf16.h>
#include <cstdint>

// Problem constants (fixed by the dataset)
#define NN   50000
#define EE   800000
#define C    128
#define COUT 64
#define EPSV 1e-5f
#define APITCH 132
#define SCAN_B 1024
#define NSCB   ((NN + SCAN_B - 1) / SCAN_B)   // 49

// ---------------- device scratch (no allocations allowed) ----------------
// Invariant: g_cnt and g_deg are ZERO at the start of every kernel_launch call.
// (zero at module load; head_kernel re-zeroes both at the end of each call.)
__device__ float g_deg[NN];
__device__ int   g_cnt[NN];
__device__ int   g_rowstart[NN + 1];
__device__ int   g_cursor[NN];
__device__ int   g_btot[NSCB];
__device__ int   g_boff[NSCB];
__device__ int   g_col[EE];
__device__ float g_wv[EE];
__device__ float g_agg[(size_t)NN * C];
__device__ float g_bufA[(size_t)NN * C];
__device__ float g_bufB[(size_t)NN * C];
__device__ float g_bnA[3 * C];
__device__ float g_bnB[3 * C];
__device__ float g_wt[5 * 128 * 128];  // transposed weights WT[n][k], tf32-rounded

__device__ __forceinline__ float to_tf32(float f) {
    uint32_t u;
    asm("cvt.rna.tf32.f32 %0, %1;" : "=r"(u) : "f"(f));
    return __uint_as_float(u);
}

__device__ __forceinline__ void mma8(float* d, const uint32_t* a, const uint32_t* b) {
    asm volatile(
        "mma.sync.aligned.m16n8k8.row.col.f32.tf32.tf32.f32 "
        "{%0,%1,%2,%3}, {%4,%5,%6,%7}, {%8,%9}, {%0,%1,%2,%3};"
        : "+f"(d[0]), "+f"(d[1]), "+f"(d[2]), "+f"(d[3])
        : "r"(a[0]), "r"(a[1]), "r"(a[2]), "r"(a[3]), "r"(b[0]), "r"(b[1]));
}

// ---------------- kernel 0: edge count/degree atomics + weight transpose ----------------
__global__ void count_tr_kernel(const int* __restrict__ dst, const float* __restrict__ ew, int e,
                                const float* __restrict__ w1, const float* __restrict__ conv_ws,
                                const float* __restrict__ lin1_w, const float* __restrict__ lin2_w) {
    int nb_e = (e + 255) / 256;
    if ((int)blockIdx.x < nb_e) {
        int i = blockIdx.x * 256 + threadIdx.x;
        if (i < e) {
            int d = dst[i];
            atomicAdd(&g_cnt[d], 1);
            atomicAdd(&g_deg[d], ew[i]);
        }
        return;
    }
    int g = (blockIdx.x - nb_e) * 256 + threadIdx.x;
    if (g < 4 * 16384) {
        int mat = g >> 14, idx = g & 16383;
        int k = idx >> 7, nn = idx & 127;
        const float* W = (mat == 0) ? w1 : ((mat == 3) ? lin1_w : (conv_ws + (mat - 1) * 16384));
        g_wt[mat * 16384 + nn * 128 + k] = to_tf32(W[k * 128 + nn]);
    } else if (g < 4 * 16384 + 8192) {
        int idx = g - 4 * 16384;
        int k = idx >> 6, nn = idx & 63;
        g_wt[4 * 16384 + nn * 128 + k] = to_tf32(lin2_w[k * 64 + nn]);
    }
}

// ---------------- scan phase A: per-block (1024-elem) exclusive scans ----------------
__global__ __launch_bounds__(SCAN_B) void scanA_kernel(int n) {
    __shared__ int wsum[32];
    int t = threadIdx.x, lane = t & 31, w = t >> 5;
    int i = blockIdx.x * SCAN_B + t;
    int v = (i < n) ? g_cnt[i] : 0;
    int x = v;
    #pragma unroll
    for (int o = 1; o < 32; o <<= 1) { int y = __shfl_up_sync(0xffffffffu, x, o); if (lane >= o) x += y; }
    if (lane == 31) wsum[w] = x;
    __syncthreads();
    if (w == 0) {
        int s = (lane < 32) ? wsum[lane] : 0;
        #pragma unroll
        for (int o = 1; o < 32; o <<= 1) { int y = __shfl_up_sync(0xffffffffu, s, o); if (lane >= o) s += y; }
        wsum[lane] = s;
    }
    __syncthreads();
    int incl = x + (w > 0 ? wsum[w - 1] : 0);
    if (i < n) g_rowstart[i] = incl - v;          // block-local exclusive
    if (t == SCAN_B - 1) g_btot[blockIdx.x] = incl;
}

// ---------------- scan phase B: scan 49 block totals (one warp) + BN fold ----------------
__global__ __launch_bounds__(128) void scanB_kernel(int n, const float* b1,
                                  const float* g1, const float* be1, const float* m1, const float* v1,
                                  const float* conv_bs,
                                  const float* gs, const float* bes, const float* ms, const float* vs) {
    int t = threadIdx.x;
    if (t < 32) {
        int run = 0;
        for (int b = t; b < NSCB + 32; b += 32) {
            int v = (b < NSCB) ? g_btot[b] : 0;
            int x = v;
            #pragma unroll
            for (int o = 1; o < 32; o <<= 1) { int y = __shfl_up_sync(0xffffffffu, x, o); if ((t & 31) >= o) x += y; }
            if (b < NSCB) g_boff[b] = run + x - v;
            int tot = __shfl_sync(0xffffffffu, x, 31);
            run += tot;
        }
        if (t == 0) g_rowstart[n] = run;
    }
    if (t < C) {
        int c = t;
        float sc = g1[c] * rsqrtf(v1[c] + EPSV);
        g_bnA[c] = sc;
        g_bnB[c] = be1[c] + (b1[c] - m1[c]) * sc;
        #pragma unroll
        for (int l = 0; l < 2; l++) {
            float s2 = gs[l * C + c] * rsqrtf(vs[l * C + c] + EPSV);
            g_bnA[(1 + l) * C + c] = s2;
            g_bnB[(1 + l) * C + c] = bes[l * C + c] + (conv_bs[l * C + c] - ms[l * C + c]) * s2;
        }
    }
}

// ---------------- scan phase C: add block offsets + dis + cursor ----------------
__global__ __launch_bounds__(SCAN_B) void scanC_kernel(int n) {
    int i = blockIdx.x * SCAN_B + threadIdx.x;
    if (i < n) {
        int rs = g_rowstart[i] + g_boff[blockIdx.x];
        g_rowstart[i] = rs;
        g_cursor[i] = rs;
        g_deg[i] = rsqrtf(g_deg[i] + 1.0f);   // + self loop
    }
}

// ---------------- CSR fill ----------------
__global__ void fill_kernel(const int* __restrict__ src, const int* __restrict__ dst,
                            const float* __restrict__ ew, int e) {
    int i = blockIdx.x * blockDim.x + threadIdx.x;
    if (i < e) {
        int s = src[i], d = dst[i];
        int pos = atomicAdd(&g_cursor[d], 1);
        g_col[pos] = s;
        g_wv[pos]  = g_deg[s] * ew[i] * g_deg[d];
    }
}

// ---------------- aggregation (R5-proven form): warp-per-row scalar gather ----------------
__global__ __launch_bounds__(256) void agg_kernel(const float* __restrict__ H, int n) {
    int wid = threadIdx.x >> 5, lane = threadIdx.x & 31;
    int m = blockIdx.x * 8 + wid;
    if (m >= n) return;

    float dis = g_deg[m];
    float w0 = dis * dis;
    float4 h4 = *reinterpret_cast<const float4*>(&H[(size_t)m * 128 + lane * 4]);
    float4 acc = make_float4(w0 * h4.x, w0 * h4.y, w0 * h4.z, w0 * h4.w);

    int s = g_rowstart[m], e = g_rowstart[m + 1];
    int k = s;
    for (; k + 8 <= e; k += 8) {
        int   c0 = __ldg(&g_col[k]),     c1 = __ldg(&g_col[k + 1]);
        int   c2 = __ldg(&g_col[k + 2]), c3 = __ldg(&g_col[k + 3]);
        int   c4 = __ldg(&g_col[k + 4]), c5 = __ldg(&g_col[k + 5]);
        int   c6 = __ldg(&g_col[k + 6]), c7 = __ldg(&g_col[k + 7]);
        float w0e = __ldg(&g_wv[k]),     w1e = __ldg(&g_wv[k + 1]);
        float w2e = __ldg(&g_wv[k + 2]), w3e = __ldg(&g_wv[k + 3]);
        float w4e = __ldg(&g_wv[k + 4]), w5e = __ldg(&g_wv[k + 5]);
        float w6e = __ldg(&g_wv[k + 6]), w7e = __ldg(&g_wv[k + 7]);
        float4 v0 = *reinterpret_cast<const float4*>(&H[(size_t)c0 * 128 + lane * 4]);
        float4 v1 = *reinterpret_cast<const float4*>(&H[(size_t)c1 * 128 + lane * 4]);
        float4 v2 = *reinterpret_cast<const float4*>(&H[(size_t)c2 * 128 + lane * 4]);
        float4 v3 = *reinterpret_cast<const float4*>(&H[(size_t)c3 * 128 + lane * 4]);
        float4 v4 = *reinterpret_cast<const float4*>(&H[(size_t)c4 * 128 + lane * 4]);
        float4 v5 = *reinterpret_cast<const float4*>(&H[(size_t)c5 * 128 + lane * 4]);
        float4 v6 = *reinterpret_cast<const float4*>(&H[(size_t)c6 * 128 + lane * 4]);
        float4 v7 = *reinterpret_cast<const float4*>(&H[(size_t)c7 * 128 + lane * 4]);
        acc.x += w0e * v0.x + w1e * v1.x + w2e * v2.x + w3e * v3.x
               + w4e * v4.x + w5e * v5.x + w6e * v6.x + w7e * v7.x;
        acc.y += w0e * v0.y + w1e * v1.y + w2e * v2.y + w3e * v3.y
               + w4e * v4.y + w5e * v5.y + w6e * v6.y + w7e * v7.y;
        acc.z += w0e * v0.z + w1e * v1.z + w2e * v2.z + w3e * v3.z
               + w4e * v4.z + w5e * v5.z + w6e * v6.z + w7e * v7.z;
        acc.w += w0e * v0.w + w1e * v1.w + w2e * v2.w + w3e * v3.w
               + w4e * v4.w + w5e * v5.w + w6e * v6.w + w7e * v7.w;
    }
    for (; k < e; k++) {
        int cc = __ldg(&g_col[k]);
        float we = __ldg(&g_wv[k]);
        float4 v = *reinterpret_cast<const float4*>(&H[(size_t)cc * 128 + lane * 4]);
        acc.x += we * v.x; acc.y += we * v.y; acc.z += we * v.z; acc.w += we * v.w;
    }
    *reinterpret_cast<float4*>(&g_agg[(size_t)m * 128 + lane * 4]) = acc;
}

// ---------------- GEMM + BN + residual + lrelu (full-K, R5 layout) ----------------
template <int HASRES>
__global__ __launch_bounds__(256) void gemm_bn_kernel(const float* __restrict__ WT,
                                                      int layer, const float* __restrict__ H,
                                                      float* __restrict__ out, int M) {
    extern __shared__ float sm[];
    float* As = sm;                    // [128][APITCH]
    float* Ws = sm + 128 * APITCH;     // [128][APITCH]

    int tid = threadIdx.x;
    int wid = tid >> 5, lane = tid & 31;
    int m0 = blockIdx.x * 128;

    #pragma unroll
    for (int it = 0; it < 16; it++) {
        int idx = tid + it * 256;
        int r = idx >> 5, q = idx & 31;
        int m = m0 + r;
        float4 v = make_float4(0.f, 0.f, 0.f, 0.f);
        if (m < M) v = *reinterpret_cast<const float4*>(&g_agg[(size_t)m * 128 + q * 4]);
        float* p = &As[r * APITCH + q * 4];
        p[0] = to_tf32(v.x); p[1] = to_tf32(v.y); p[2] = to_tf32(v.z); p[3] = to_tf32(v.w);
    }
    #pragma unroll
    for (int it = 0; it < 16; it++) {
        int idx = tid + it * 256;
        int r = idx >> 5, q = idx & 31;
        float4 v = *reinterpret_cast<const float4*>(&WT[(size_t)r * 128 + q * 4]);
        *reinterpret_cast<float4*>(&Ws[r * APITCH + q * 4]) = v;
    }
    __syncthreads();

    int wm = wid & 3, wn = wid >> 2;
    int grp = lane >> 2, tg = lane & 3;
    int arow = wm * 32 + grp;
    int brow = wn * 64 + grp;

    float d[2][8][4];
    #pragma unroll
    for (int i = 0; i < 2; i++)
        #pragma unroll
        for (int j = 0; j < 8; j++)
            #pragma unroll
            for (int q = 0; q < 4; q++) d[i][j][q] = 0.0f;

    #pragma unroll
    for (int k0 = 0; k0 < 16; k0++) {
        int kk = k0 * 8 + tg;
        uint32_t a[2][4];
        #pragma unroll
        for (int mf = 0; mf < 2; mf++) {
            const float* ap = &As[(arow + mf * 16) * APITCH + kk];
            a[mf][0] = __float_as_uint(ap[0]);
            a[mf][2] = __float_as_uint(ap[4]);
            a[mf][1] = __float_as_uint(ap[8 * APITCH]);
            a[mf][3] = __float_as_uint(ap[8 * APITCH + 4]);
        }
        uint32_t b[8][2];
        #pragma unroll
        for (int nf = 0; nf < 8; nf++) {
            const float* bp = &Ws[(brow + nf * 8) * APITCH + kk];
            b[nf][0] = __float_as_uint(bp[0]);
            b[nf][1] = __float_as_uint(bp[4]);
        }
        #pragma unroll
        for (int mf = 0; mf < 2; mf++)
            #pragma unroll
            for (int nf = 0; nf < 8; nf++)
                mma8(d[mf][nf], a[mf], b[nf]);
    }

    const float* bnA = &g_bnA[layer * C];
    const float* bnB = &g_bnB[layer * C];
    #pragma unroll
    for (int mf = 0; mf < 2; mf++) {
        #pragma unroll
        for (int half = 0; half < 2; half++) {
            int m = m0 + wm * 32 + mf * 16 + half * 8 + grp;
            if (m < M) {
                #pragma unroll
                for (int nf = 0; nf < 8; nf++) {
                    int ncol = wn * 64 + nf * 8 + tg * 2;
                    float2 v;
                    v.x = d[mf][nf][half * 2 + 0] * bnA[ncol]     + bnB[ncol];
                    v.y = d[mf][nf][half * 2 + 1] * bnA[ncol + 1] + bnB[ncol + 1];
                    if (HASRES) {
                        float2 rv = *reinterpret_cast<const float2*>(&H[(size_t)m * 128 + ncol]);
                        v.x += rv.x; v.y += rv.y;
                    }
                    v.x = v.x > 0.f ? v.x : 0.01f * v.x;
                    v.y = v.y > 0.f ? v.y : 0.01f * v.y;
                    *reinterpret_cast<float2*>(&out[(size_t)m * 128 + ncol]) = v;
                }
            }
        }
    }
}

// ---------------- fused head + invariant restore (g_cnt, g_deg -> 0) ----------------
__global__ __launch_bounds__(256) void head_kernel(const float* __restrict__ H,
                                                   const float* __restrict__ WT1,
                                                   const float* __restrict__ bias1,
                                                   const float* __restrict__ WT2,
                                                   const float* __restrict__ bias2,
                                                   float* __restrict__ out, int M) {
    extern __shared__ float sm[];
    float* As  = sm;                          // [128][APITCH]
    float* W1s = sm + 128 * APITCH;           // [128][APITCH]
    float* W2s = sm + 256 * APITCH;           // [64][APITCH]

    int tid = threadIdx.x;
    int wid = tid >> 5, lane = tid & 31;
    int m0 = blockIdx.x * 128;

    // restore zero invariant (head runs after last use of g_deg / g_cnt)
    {
        int z = blockIdx.x * 256 + tid;
        if (z < NN) { g_deg[z] = 0.0f; g_cnt[z] = 0; }
    }

    #pragma unroll
    for (int it = 0; it < 16; it++) {
        int idx = tid + it * 256;
        int r = idx >> 5, q = idx & 31;
        int m = m0 + r;
        float4 v = make_float4(0.f, 0.f, 0.f, 0.f);
        if (m < M) v = *reinterpret_cast<const float4*>(&H[(size_t)m * 128 + q * 4]);
        float* p = &As[r * APITCH + q * 4];
        p[0] = to_tf32(v.x); p[1] = to_tf32(v.y); p[2] = to_tf32(v.z); p[3] = to_tf32(v.w);
    }
    #pragma unroll
    for (int it = 0; it < 16; it++) {
        int idx = tid + it * 256;
        int r = idx >> 5, q = idx & 31;
        float4 v = *reinterpret_cast<const float4*>(&WT1[(size_t)r * 128 + q * 4]);
        *reinterpret_cast<float4*>(&W1s[r * APITCH + q * 4]) = v;
    }
    #pragma unroll
    for (int it = 0; it < 8; it++) {
        int idx = tid + it * 256;
        int r = idx >> 5, q = idx & 31;
        float4 v = *reinterpret_cast<const float4*>(&WT2[(size_t)r * 128 + q * 4]);
        *reinterpret_cast<float4*>(&W2s[r * APITCH + q * 4]) = v;
    }
    __syncthreads();

    int wm = wid & 3, wn = wid >> 2;
    int grp = lane >> 2, tg = lane & 3;
    int arow = wm * 32 + grp;

    // ---- MMA1: z = H @ lin1 ----
    {
        int brow = wn * 64 + grp;
        float d[2][8][4];
        #pragma unroll
        for (int i = 0; i < 2; i++)
            #pragma unroll
            for (int j = 0; j < 8; j++)
                #pragma unroll
                for (int q = 0; q < 4; q++) d[i][j][q] = 0.0f;

        #pragma unroll
        for (int k0 = 0; k0 < 16; k0++) {
            int kk = k0 * 8 + tg;
            uint32_t a[2][4];
            #pragma unroll
            for (int mf = 0; mf < 2; mf++) {
                const float* ap = &As[(arow + mf * 16) * APITCH + kk];
                a[mf][0] = __float_as_uint(ap[0]);
                a[mf][2] = __float_as_uint(ap[4]);
                a[mf][1] = __float_as_uint(ap[8 * APITCH]);
                a[mf][3] = __float_as_uint(ap[8 * APITCH + 4]);
            }
            uint32_t b[8][2];
            #pragma unroll
            for (int nf = 0; nf < 8; nf++) {
                const float* bp = &W1s[(brow + nf * 8) * APITCH + kk];
                b[nf][0] = __float_as_uint(bp[0]);
                b[nf][1] = __float_as_uint(bp[4]);
            }
            #pragma unroll
            for (int mf = 0; mf < 2; mf++)
                #pragma unroll
                for (int nf = 0; nf < 8; nf++)
                    mma8(d[mf][nf], a[mf], b[nf]);
        }
        __syncthreads();

        #pragma unroll
        for (int mf = 0; mf < 2; mf++) {
            #pragma unroll
            for (int half = 0; half < 2; half++) {
                int r = wm * 32 + mf * 16 + half * 8 + grp;
                #pragma unroll
                for (int nf = 0; nf < 8; nf++) {
                    int ncol = wn * 64 + nf * 8 + tg * 2;
                    float vx = d[mf][nf][half * 2 + 0] + bias1[ncol];
                    float vy = d[mf][nf][half * 2 + 1] + bias1[ncol + 1];
                    vx = vx > 0.f ? vx : 0.01f * vx;
                    vy = vy > 0.f ? vy : 0.01f * vy;
                    As[r * APITCH + ncol]     = to_tf32(vx);
                    As[r * APITCH + ncol + 1] = to_tf32(vy);
                }
            }
        }
        __syncthreads();
    }

    // ---- MMA2: out = z @ lin2 ----
    {
        int brow = wn * 32 + grp;
        float d[2][4][4];
        #pragma unroll
        for (int i = 0; i < 2; i++)
            #pragma unroll
            for (int j = 0; j < 4; j++)
                #pragma unroll
                for (int q = 0; q < 4; q++) d[i][j][q] = 0.0f;

        #pragma unroll
        for (int k0 = 0; k0 < 16; k0++) {
            int kk = k0 * 8 + tg;
            uint32_t a[2][4];
            #pragma unroll
            for (int mf = 0; mf < 2; mf++) {
                const float* ap = &As[(arow + mf * 16) * APITCH + kk];
                a[mf][0] = __float_as_uint(ap[0]);
                a[mf][2] = __float_as_uint(ap[4]);
                a[mf][1] = __float_as_uint(ap[8 * APITCH]);
                a[mf][3] = __float_as_uint(ap[8 * APITCH + 4]);
            }
            uint32_t b[4][2];
            #pragma unroll
            for (int nf = 0; nf < 4; nf++) {
                const float* bp = &W2s[(brow + nf * 8) * APITCH + kk];
                b[nf][0] = __float_as_uint(bp[0]);
                b[nf][1] = __float_as_uint(bp[4]);
            }
            #pragma unroll
            for (int mf = 0; mf < 2; mf++)
                #pragma unroll
                for (int nf = 0; nf < 4; nf++)
                    mma8(d[mf][nf], a[mf], b[nf]);
        }

        #pragma unroll
        for (int mf = 0; mf < 2; mf++) {
            #pragma unroll
            for (int half = 0; half < 2; half++) {
                int m = m0 + wm * 32 + mf * 16 + half * 8 + grp;
                if (m < M) {
                    #pragma unroll
                    for (int nf = 0; nf < 4; nf++) {
                        int ncol = wn * 32 + nf * 8 + tg * 2;
                        float2 v;
                        v.x = d[mf][nf][half * 2 + 0] + bias2[ncol];
                        v.y = d[mf][nf][half * 2 + 1] + bias2[ncol + 1];
                        *reinterpret_cast<float2*>(&out[(size_t)m * COUT + ncol]) = v;
                    }
                }
            }
        }
    }
}

// ---------------- launch ----------------
extern "C" void kernel_launch(void* const* d_in, const int* in_sizes, int n_in,
                              void* d_out, int out_size) {
    const float* x       = (const float*)d_in[0];
    const int*   ei      = (const int*)d_in[1];
    const float* ew      = (const float*)d_in[2];
    const float* w1      = (const float*)d_in[3];
    const float* b1      = (const float*)d_in[4];
    const float* bn1_g   = (const float*)d_in[5];
    const float* bn1_b   = (const float*)d_in[6];
    const float* bn1_m   = (const float*)d_in[7];
    const float* bn1_v   = (const float*)d_in[8];
    const float* conv_ws = (const float*)d_in[9];
    const float* conv_bs = (const float*)d_in[10];
    const float* bns_g   = (const float*)d_in[11];
    const float* bns_b   = (const float*)d_in[12];
    const float* bns_m   = (const float*)d_in[13];
    const float* bns_v   = (const float*)d_in[14];
    const float* lin1_w  = (const float*)d_in[15];
    const float* lin1_b  = (const float*)d_in[16];
    const float* lin2_w  = (const float*)d_in[17];
    const float* lin2_b  = (const float*)d_in[18];

    int n = in_sizes[0] / C;     // 50000
    int e = in_sizes[2];         // 800000
    const int* srcp = ei;
    const int* dstp = ei + e;

    const int SMEM_GEMM = 256 * APITCH * 4;   // 135168
    const int SMEM_HEAD = 320 * APITCH * 4;   // 168960

    cudaFuncSetAttribute(gemm_bn_kernel<0>, cudaFuncAttributeMaxDynamicSharedMemorySize, SMEM_GEMM);
    cudaFuncSetAttribute(gemm_bn_kernel<1>, cudaFuncAttributeMaxDynamicSharedMemorySize, SMEM_GEMM);
    cudaFuncSetAttribute(head_kernel,       cudaFuncAttributeMaxDynamicSharedMemorySize, SMEM_HEAD);

    float* wt = nullptr;   cudaGetSymbolAddress((void**)&wt, g_wt);
    float* bufA = nullptr; cudaGetSymbolAddress((void**)&bufA, g_bufA);
    float* bufB = nullptr; cudaGetSymbolAddress((void**)&bufB, g_bufB);

    int nb_e = (e + 255) / 256;
    int nb_s = (n + SCAN_B - 1) / SCAN_B;

    count_tr_kernel<<<nb_e + (5 * 16384 - 8192 + 255) / 256, 256>>>(dstp, ew, e, w1, conv_ws, lin1_w, lin2_w);
    scanA_kernel<<<nb_s, SCAN_B>>>(n);
    scanB_kernel<<<1, 128>>>(n, b1, bn1_g, bn1_b, bn1_m, bn1_v,
                             conv_bs, bns_g, bns_b, bns_m, bns_v);
    scanC_kernel<<<nb_s, SCAN_B>>>(n);        // <- ncu capture slot
    fill_kernel<<<nb_e, 256>>>(srcp, dstp, ew, e);

    int ablocks = (n + 7) / 8;
    int gblocks = (n + 127) / 128;

    // layer 0
    agg_kernel<<<ablocks, 256>>>(x, n);
    gemm_bn_kernel<0><<<gblocks, 256, SMEM_GEMM>>>(wt + 0 * 16384, 0, nullptr, bufA, n);

    // layer 1
    agg_kernel<<<ablocks, 256>>>(bufA, n);
    gemm_bn_kernel<1><<<gblocks, 256, SMEM_GEMM>>>(wt + 1 * 16384, 1, bufA, bufB, n);

    // layer 2
    agg_kernel<<<ablocks, 256>>>(bufB, n);
    gemm_bn_kernel<1><<<gblocks, 256, SMEM_GEMM>>>(wt + 2 * 16384, 2, bufB, bufA, n);

    // fused heads (also restores g_cnt/g_deg = 0)
    head_kernel<<<gblocks, 256, SMEM_HEAD>>>(bufA, wt + 3 * 16384, lin1_b, wt + 4 * 16384, lin2_b,
                                             (float*)d_out, n);
}

// round 11
// speedup vs baseline: 1.4298x; 1.0736x over previous
#include <cuda_runtime.h>
#include <cuda_bf16.h>
#include <cstdint>

// Problem constants (fixed by the dataset)
#define NN   50000
#define EE   800000
#define C    128
#define COUT 64
#define EPSV 1e-5f
#define APITCH 132
#define SCAN_B 1024
#define NSCB   ((NN + SCAN_B - 1) / SCAN_B)   // 49

// ---------------- device scratch (no allocations allowed) ----------------
// Invariant: g_cnt, g_deg, g_bflag are ZERO at the start of every call.
// (zero at module load; tail_kernel re-zeroes all three at the end of each call.)
__device__ float g_deg[NN];
__device__ int   g_cnt[NN];
__device__ int   g_rowstart[NN + 1];
__device__ int   g_cursor[NN];
__device__ int   g_btot[NSCB];
__device__ int   g_bflag[NSCB];
__device__ int   g_col[EE];
__device__ float g_wv[EE];
__device__ float g_agg[(size_t)NN * C];
__device__ float g_bufA[(size_t)NN * C];
__device__ float g_bufB[(size_t)NN * C];
__device__ float g_bnA[3 * C];
__device__ float g_bnB[3 * C];
__device__ float g_wt[5 * 128 * 128];  // transposed weights WT[n][k], tf32-rounded

__device__ __forceinline__ float to_tf32(float f) {
    uint32_t u;
    asm("cvt.rna.tf32.f32 %0, %1;" : "=r"(u) : "f"(f));
    return __uint_as_float(u);
}

__device__ __forceinline__ void mma8(float* d, const uint32_t* a, const uint32_t* b) {
    asm volatile(
        "mma.sync.aligned.m16n8k8.row.col.f32.tf32.tf32.f32 "
        "{%0,%1,%2,%3}, {%4,%5,%6,%7}, {%8,%9}, {%0,%1,%2,%3};"
        : "+f"(d[0]), "+f"(d[1]), "+f"(d[2]), "+f"(d[3])
        : "r"(a[0]), "r"(a[1]), "r"(a[2]), "r"(a[3]), "r"(b[0]), "r"(b[1]));
}

// ---------------- kernel 0: edge count/degree atomics + weight transpose ----------------
__global__ void count_tr_kernel(const int* __restrict__ dst, const float* __restrict__ ew, int e,
                                const float* __restrict__ w1, const float* __restrict__ conv_ws,
                                const float* __restrict__ lin1_w, const float* __restrict__ lin2_w) {
    int nb_e = (e + 255) / 256;
    if ((int)blockIdx.x < nb_e) {
        int i = blockIdx.x * 256 + threadIdx.x;
        if (i < e) {
            int d = dst[i];
            atomicAdd(&g_cnt[d], 1);
            atomicAdd(&g_deg[d], ew[i]);
        }
        return;
    }
    int g = (blockIdx.x - nb_e) * 256 + threadIdx.x;
    if (g < 4 * 16384) {
        int mat = g >> 14, idx = g & 16383;
        int k = idx >> 7, nn = idx & 127;
        const float* W = (mat == 0) ? w1 : ((mat == 3) ? lin1_w : (conv_ws + (mat - 1) * 16384));
        g_wt[mat * 16384 + nn * 128 + k] = to_tf32(W[k * 128 + nn]);
    } else if (g < 4 * 16384 + 8192) {
        int idx = g - 4 * 16384;
        int k = idx >> 6, nn = idx & 63;
        g_wt[4 * 16384 + nn * 128 + k] = to_tf32(lin2_w[k * 64 + nn]);
    }
}

// ---------------- single-pass scan (decoupled lookback) + dis + cursor + BN fold ----------------
// 49 blocks of 1024 — all resident simultaneously on 148 SMs, so the spin is safe.
__global__ __launch_bounds__(SCAN_B) void scan_kernel(int n, const float* b1,
                                  const float* g1, const float* be1, const float* m1, const float* v1,
                                  const float* conv_bs,
                                  const float* gs, const float* bes, const float* ms, const float* vs) {
    __shared__ int wsum[32];
    __shared__ int s_prefix;
    int t = threadIdx.x, lane = t & 31, w = t >> 5;
    int b = blockIdx.x;
    int i = b * SCAN_B + t;

    int v = (i < n) ? g_cnt[i] : 0;
    int x = v;
    #pragma unroll
    for (int o = 1; o < 32; o <<= 1) { int y = __shfl_up_sync(0xffffffffu, x, o); if (lane >= o) x += y; }
    if (lane == 31) wsum[w] = x;
    __syncthreads();
    if (w == 0) {
        int s = wsum[lane];
        #pragma unroll
        for (int o = 1; o < 32; o <<= 1) { int y = __shfl_up_sync(0xffffffffu, s, o); if (lane >= o) s += y; }
        wsum[lane] = s;
    }
    __syncthreads();
    int incl = x + (w > 0 ? wsum[w - 1] : 0);   // block-local inclusive
    int btotal = wsum[31];

    // publish this block's total
    if (t == 0) {
        atomicExch(&g_btot[b], btotal);
        __threadfence();
        atomicExch(&g_bflag[b], 1);
    }

    // lookback: warp 1 sums totals of all predecessor blocks
    if (w == 1) {
        int sum = 0;
        for (int j = lane; j < b; j += 32) {
            while (atomicAdd(&g_bflag[j], 0) == 0) {}
            sum += atomicAdd(&g_btot[j], 0);
        }
        #pragma unroll
        for (int o = 16; o > 0; o >>= 1) sum += __shfl_down_sync(0xffffffffu, sum, o);
        if (lane == 0) s_prefix = sum;
    }
    __syncthreads();
    int prefix = s_prefix;

    if (i < n) {
        int rs = prefix + incl - v;
        g_rowstart[i] = rs;
        g_cursor[i] = rs;
        g_deg[i] = rsqrtf(g_deg[i] + 1.0f);   // + self loop
    }
    if (b == NSCB - 1 && t == 0) g_rowstart[n] = prefix + btotal;

    // BN fold (block 0)
    if (b == 0 && t < C) {
        int c = t;
        float sc = g1[c] * rsqrtf(v1[c] + EPSV);
        g_bnA[c] = sc;
        g_bnB[c] = be1[c] + (b1[c] - m1[c]) * sc;
        #pragma unroll
        for (int l = 0; l < 2; l++) {
            float s2 = gs[l * C + c] * rsqrtf(vs[l * C + c] + EPSV);
            g_bnA[(1 + l) * C + c] = s2;
            g_bnB[(1 + l) * C + c] = bes[l * C + c] + (conv_bs[l * C + c] - ms[l * C + c]) * s2;
        }
    }
}

// ---------------- CSR fill ----------------
__global__ void fill_kernel(const int* __restrict__ src, const int* __restrict__ dst,
                            const float* __restrict__ ew, int e) {
    int i = blockIdx.x * blockDim.x + threadIdx.x;
    if (i < e) {
        int s = src[i], d = dst[i];
        int pos = atomicAdd(&g_cursor[d], 1);
        g_col[pos] = s;
        g_wv[pos]  = g_deg[s] * ew[i] * g_deg[d];
    }
}

// ---------------- aggregation (R5-proven form): warp-per-row scalar gather ----------------
__global__ __launch_bounds__(256) void agg_kernel(const float* __restrict__ H, int n) {
    int wid = threadIdx.x >> 5, lane = threadIdx.x & 31;
    int m = blockIdx.x * 8 + wid;
    if (m >= n) return;

    float dis = g_deg[m];
    float w0 = dis * dis;
    float4 h4 = *reinterpret_cast<const float4*>(&H[(size_t)m * 128 + lane * 4]);
    float4 acc = make_float4(w0 * h4.x, w0 * h4.y, w0 * h4.z, w0 * h4.w);

    int s = g_rowstart[m], e = g_rowstart[m + 1];
    int k = s;
    for (; k + 8 <= e; k += 8) {
        int   c0 = __ldg(&g_col[k]),     c1 = __ldg(&g_col[k + 1]);
        int   c2 = __ldg(&g_col[k + 2]), c3 = __ldg(&g_col[k + 3]);
        int   c4 = __ldg(&g_col[k + 4]), c5 = __ldg(&g_col[k + 5]);
        int   c6 = __ldg(&g_col[k + 6]), c7 = __ldg(&g_col[k + 7]);
        float w0e = __ldg(&g_wv[k]),     w1e = __ldg(&g_wv[k + 1]);
        float w2e = __ldg(&g_wv[k + 2]), w3e = __ldg(&g_wv[k + 3]);
        float w4e = __ldg(&g_wv[k + 4]), w5e = __ldg(&g_wv[k + 5]);
        float w6e = __ldg(&g_wv[k + 6]), w7e = __ldg(&g_wv[k + 7]);
        float4 v0 = *reinterpret_cast<const float4*>(&H[(size_t)c0 * 128 + lane * 4]);
        float4 v1 = *reinterpret_cast<const float4*>(&H[(size_t)c1 * 128 + lane * 4]);
        float4 v2 = *reinterpret_cast<const float4*>(&H[(size_t)c2 * 128 + lane * 4]);
        float4 v3 = *reinterpret_cast<const float4*>(&H[(size_t)c3 * 128 + lane * 4]);
        float4 v4 = *reinterpret_cast<const float4*>(&H[(size_t)c4 * 128 + lane * 4]);
        float4 v5 = *reinterpret_cast<const float4*>(&H[(size_t)c5 * 128 + lane * 4]);
        float4 v6 = *reinterpret_cast<const float4*>(&H[(size_t)c6 * 128 + lane * 4]);
        float4 v7 = *reinterpret_cast<const float4*>(&H[(size_t)c7 * 128 + lane * 4]);
        acc.x += w0e * v0.x + w1e * v1.x + w2e * v2.x + w3e * v3.x
               + w4e * v4.x + w5e * v5.x + w6e * v6.x + w7e * v7.x;
        acc.y += w0e * v0.y + w1e * v1.y + w2e * v2.y + w3e * v3.y
               + w4e * v4.y + w5e * v5.y + w6e * v6.y + w7e * v7.y;
        acc.z += w0e * v0.z + w1e * v1.z + w2e * v2.z + w3e * v3.z
               + w4e * v4.z + w5e * v5.z + w6e * v6.z + w7e * v7.z;
        acc.w += w0e * v0.w + w1e * v1.w + w2e * v2.w + w3e * v3.w
               + w4e * v4.w + w5e * v5.w + w6e * v6.w + w7e * v7.w;
    }
    for (; k < e; k++) {
        int cc = __ldg(&g_col[k]);
        float we = __ldg(&g_wv[k]);
        float4 v = *reinterpret_cast<const float4*>(&H[(size_t)cc * 128 + lane * 4]);
        acc.x += we * v.x; acc.y += we * v.y; acc.z += we * v.z; acc.w += we * v.w;
    }
    *reinterpret_cast<float4*>(&g_agg[(size_t)m * 128 + lane * 4]) = acc;
}

// ---------------- GEMM + BN + residual + lrelu (layers 0,1) ----------------
template <int HASRES>
__global__ __launch_bounds__(256) void gemm_bn_kernel(const float* __restrict__ WT,
                                                      int layer, const float* __restrict__ H,
                                                      float* __restrict__ out, int M) {
    extern __shared__ float sm[];
    float* As = sm;                    // [128][APITCH]
    float* Ws = sm + 128 * APITCH;     // [128][APITCH]

    int tid = threadIdx.x;
    int wid = tid >> 5, lane = tid & 31;
    int m0 = blockIdx.x * 128;

    #pragma unroll
    for (int it = 0; it < 16; it++) {
        int idx = tid + it * 256;
        int r = idx >> 5, q = idx & 31;
        int m = m0 + r;
        float4 v = make_float4(0.f, 0.f, 0.f, 0.f);
        if (m < M) v = *reinterpret_cast<const float4*>(&g_agg[(size_t)m * 128 + q * 4]);
        float* p = &As[r * APITCH + q * 4];
        p[0] = to_tf32(v.x); p[1] = to_tf32(v.y); p[2] = to_tf32(v.z); p[3] = to_tf32(v.w);
    }
    #pragma unroll
    for (int it = 0; it < 16; it++) {
        int idx = tid + it * 256;
        int r = idx >> 5, q = idx & 31;
        float4 v = *reinterpret_cast<const float4*>(&WT[(size_t)r * 128 + q * 4]);
        *reinterpret_cast<float4*>(&Ws[r * APITCH + q * 4]) = v;
    }
    __syncthreads();

    int wm = wid & 3, wn = wid >> 2;
    int grp = lane >> 2, tg = lane & 3;
    int arow = wm * 32 + grp;
    int brow = wn * 64 + grp;

    float d[2][8][4];
    #pragma unroll
    for (int i = 0; i < 2; i++)
        #pragma unroll
        for (int j = 0; j < 8; j++)
            #pragma unroll
            for (int q = 0; q < 4; q++) d[i][j][q] = 0.0f;

    #pragma unroll
    for (int k0 = 0; k0 < 16; k0++) {
        int kk = k0 * 8 + tg;
        uint32_t a[2][4];
        #pragma unroll
        for (int mf = 0; mf < 2; mf++) {
            const float* ap = &As[(arow + mf * 16) * APITCH + kk];
            a[mf][0] = __float_as_uint(ap[0]);
            a[mf][2] = __float_as_uint(ap[4]);
            a[mf][1] = __float_as_uint(ap[8 * APITCH]);
            a[mf][3] = __float_as_uint(ap[8 * APITCH + 4]);
        }
        uint32_t b[8][2];
        #pragma unroll
        for (int nf = 0; nf < 8; nf++) {
            const float* bp = &Ws[(brow + nf * 8) * APITCH + kk];
            b[nf][0] = __float_as_uint(bp[0]);
            b[nf][1] = __float_as_uint(bp[4]);
        }
        #pragma unroll
        for (int mf = 0; mf < 2; mf++)
            #pragma unroll
            for (int nf = 0; nf < 8; nf++)
                mma8(d[mf][nf], a[mf], b[nf]);
    }

    const float* bnA = &g_bnA[layer * C];
    const float* bnB = &g_bnB[layer * C];
    #pragma unroll
    for (int mf = 0; mf < 2; mf++) {
        #pragma unroll
        for (int half = 0; half < 2; half++) {
            int m = m0 + wm * 32 + mf * 16 + half * 8 + grp;
            if (m < M) {
                #pragma unroll
                for (int nf = 0; nf < 8; nf++) {
                    int ncol = wn * 64 + nf * 8 + tg * 2;
                    float2 v;
                    v.x = d[mf][nf][half * 2 + 0] * bnA[ncol]     + bnB[ncol];
                    v.y = d[mf][nf][half * 2 + 1] * bnA[ncol + 1] + bnB[ncol + 1];
                    if (HASRES) {
                        float2 rv = *reinterpret_cast<const float2*>(&H[(size_t)m * 128 + ncol]);
                        v.x += rv.x; v.y += rv.y;
                    }
                    v.x = v.x > 0.f ? v.x : 0.01f * v.x;
                    v.y = v.y > 0.f ? v.y : 0.01f * v.y;
                    *reinterpret_cast<float2*>(&out[(size_t)m * 128 + ncol]) = v;
                }
            }
        }
    }
}

// ---------------- fused tail: layer-2 GEMM+BN+res+lrelu -> lin1+lrelu -> lin2 -> out ----------------
// smem: As[128][APITCH] data tile + Ws[128][APITCH] weight staging (cycled 3x).
// Also restores the zero invariants (g_cnt, g_deg, g_bflag).
__global__ __launch_bounds__(256) void tail_kernel(const float* __restrict__ H,      // residual (bufB)
                                                   const float* __restrict__ WcT,    // conv_w2
                                                   const float* __restrict__ WT1,
                                                   const float* __restrict__ bias1,
                                                   const float* __restrict__ WT2,
                                                   const float* __restrict__ bias2,
                                                   float* __restrict__ out, int M) {
    extern __shared__ float sm[];
    float* As = sm;                    // [128][APITCH]
    float* Ws = sm + 128 * APITCH;     // [128][APITCH]

    int tid = threadIdx.x;
    int wid = tid >> 5, lane = tid & 31;
    int m0 = blockIdx.x * 128;

    // restore zero invariants
    {
        int z = blockIdx.x * 256 + tid;
        if (z < NN) { g_deg[z] = 0.0f; g_cnt[z] = 0; }
        if (z < NSCB) g_bflag[z] = 0;
    }

    int wm = wid & 3, wn = wid >> 2;
    int grp = lane >> 2, tg = lane & 3;
    int arow = wm * 32 + grp;

    // stage As = tf32(g_agg tile), Ws = conv_w2
    #pragma unroll
    for (int it = 0; it < 16; it++) {
        int idx = tid + it * 256;
        int r = idx >> 5, q = idx & 31;
        int m = m0 + r;
        float4 v = make_float4(0.f, 0.f, 0.f, 0.f);
        if (m < M) v = *reinterpret_cast<const float4*>(&g_agg[(size_t)m * 128 + q * 4]);
        float* p = &As[r * APITCH + q * 4];
        p[0] = to_tf32(v.x); p[1] = to_tf32(v.y); p[2] = to_tf32(v.z); p[3] = to_tf32(v.w);
    }
    #pragma unroll
    for (int it = 0; it < 16; it++) {
        int idx = tid + it * 256;
        int r = idx >> 5, q = idx & 31;
        float4 v = *reinterpret_cast<const float4*>(&WcT[(size_t)r * 128 + q * 4]);
        *reinterpret_cast<float4*>(&Ws[r * APITCH + q * 4]) = v;
    }
    __syncthreads();

    float d[2][8][4];

    // ---- stage 0: layer-2 GEMM ----
    {
        int brow = wn * 64 + grp;
        #pragma unroll
        for (int i = 0; i < 2; i++)
            #pragma unroll
            for (int j = 0; j < 8; j++)
                #pragma unroll
                for (int q = 0; q < 4; q++) d[i][j][q] = 0.0f;
        #pragma unroll
        for (int k0 = 0; k0 < 16; k0++) {
            int kk = k0 * 8 + tg;
            uint32_t a[2][4];
            #pragma unroll
            for (int mf = 0; mf < 2; mf++) {
                const float* ap = &As[(arow + mf * 16) * APITCH + kk];
                a[mf][0] = __float_as_uint(ap[0]);
                a[mf][2] = __float_as_uint(ap[4]);
                a[mf][1] = __float_as_uint(ap[8 * APITCH]);
                a[mf][3] = __float_as_uint(ap[8 * APITCH + 4]);
            }
            uint32_t b[8][2];
            #pragma unroll
            for (int nf = 0; nf < 8; nf++) {
                const float* bp = &Ws[(brow + nf * 8) * APITCH + kk];
                b[nf][0] = __float_as_uint(bp[0]);
                b[nf][1] = __float_as_uint(bp[4]);
            }
            #pragma unroll
            for (int mf = 0; mf < 2; mf++)
                #pragma unroll
                for (int nf = 0; nf < 8; nf++)
                    mma8(d[mf][nf], a[mf], b[nf]);
        }
    }
    __syncthreads();   // done reading As/Ws

    // z0 = lrelu(bn2(d) + residual)  -> As (tf32) ; concurrently stage Ws = lin1
    {
        const float* bnA = &g_bnA[2 * C];
        const float* bnB = &g_bnB[2 * C];
        #pragma unroll
        for (int mf = 0; mf < 2; mf++) {
            #pragma unroll
            for (int half = 0; half < 2; half++) {
                int r = wm * 32 + mf * 16 + half * 8 + grp;
                int m = m0 + r;
                #pragma unroll
                for (int nf = 0; nf < 8; nf++) {
                    int ncol = wn * 64 + nf * 8 + tg * 2;
                    float vx = d[mf][nf][half * 2 + 0] * bnA[ncol]     + bnB[ncol];
                    float vy = d[mf][nf][half * 2 + 1] * bnA[ncol + 1] + bnB[ncol + 1];
                    if (m < M) {
                        float2 rv = *reinterpret_cast<const float2*>(&H[(size_t)m * 128 + ncol]);
                        vx += rv.x; vy += rv.y;
                    }
                    vx = vx > 0.f ? vx : 0.01f * vx;
                    vy = vy > 0.f ? vy : 0.01f * vy;
                    As[r * APITCH + ncol]     = to_tf32(vx);
                    As[r * APITCH + ncol + 1] = to_tf32(vy);
                }
            }
        }
        #pragma unroll
        for (int it = 0; it < 16; it++) {
            int idx = tid + it * 256;
            int r = idx >> 5, q = idx & 31;
            float4 v = *reinterpret_cast<const float4*>(&WT1[(size_t)r * 128 + q * 4]);
            *reinterpret_cast<float4*>(&Ws[r * APITCH + q * 4]) = v;
        }
    }
    __syncthreads();

    // ---- stage 1: lin1 ----
    {
        int brow = wn * 64 + grp;
        #pragma unroll
        for (int i = 0; i < 2; i++)
            #pragma unroll
            for (int j = 0; j < 8; j++)
                #pragma unroll
                for (int q = 0; q < 4; q++) d[i][j][q] = 0.0f;
        #pragma unroll
        for (int k0 = 0; k0 < 16; k0++) {
            int kk = k0 * 8 + tg;
            uint32_t a[2][4];
            #pragma unroll
            for (int mf = 0; mf < 2; mf++) {
                const float* ap = &As[(arow + mf * 16) * APITCH + kk];
                a[mf][0] = __float_as_uint(ap[0]);
                a[mf][2] = __float_as_uint(ap[4]);
                a[mf][1] = __float_as_uint(ap[8 * APITCH]);
                a[mf][3] = __float_as_uint(ap[8 * APITCH + 4]);
            }
            uint32_t b[8][2];
            #pragma unroll
            for (int nf = 0; nf < 8; nf++) {
                const float* bp = &Ws[(brow + nf * 8) * APITCH + kk];
                b[nf][0] = __float_as_uint(bp[0]);
                b[nf][1] = __float_as_uint(bp[4]);
            }
            #pragma unroll
            for (int mf = 0; mf < 2; mf++)
                #pragma unroll
                for (int nf = 0; nf < 8; nf++)
                    mma8(d[mf][nf], a[mf], b[nf]);
        }
    }
    __syncthreads();

    // z1 = lrelu(d + bias1) -> As (tf32) ; stage Ws = lin2 (64 rows)
    {
        #pragma unroll
        for (int mf = 0; mf < 2; mf++) {
            #pragma unroll
            for (int half = 0; half < 2; half++) {
                int r = wm * 32 + mf * 16 + half * 8 + grp;
                #pragma unroll
                for (int nf = 0; nf < 8; nf++) {
                    int ncol = wn * 64 + nf * 8 + tg * 2;
                    float vx = d[mf][nf][half * 2 + 0] + bias1[ncol];
                    float vy = d[mf][nf][half * 2 + 1] + bias1[ncol + 1];
                    vx = vx > 0.f ? vx : 0.01f * vx;
                    vy = vy > 0.f ? vy : 0.01f * vy;
                    As[r * APITCH + ncol]     = to_tf32(vx);
                    As[r * APITCH + ncol + 1] = to_tf32(vy);
                }
            }
        }
        #pragma unroll
        for (int it = 0; it < 8; it++) {
            int idx = tid + it * 256;
            int r = idx >> 5, q = idx & 31;
            float4 v = *reinterpret_cast<const float4*>(&WT2[(size_t)r * 128 + q * 4]);
            *reinterpret_cast<float4*>(&Ws[r * APITCH + q * 4]) = v;
        }
    }
    __syncthreads();

    // ---- stage 2: lin2 -> gmem ----
    {
        int brow = wn * 32 + grp;
        float d2[2][4][4];
        #pragma unroll
        for (int i = 0; i < 2; i++)
            #pragma unroll
            for (int j = 0; j < 4; j++)
                #pragma unroll
                for (int q = 0; q < 4; q++) d2[i][j][q] = 0.0f;
        #pragma unroll
        for (int k0 = 0; k0 < 16; k0++) {
            int kk = k0 * 8 + tg;
            uint32_t a[2][4];
            #pragma unroll
            for (int mf = 0; mf < 2; mf++) {
                const float* ap = &As[(arow + mf * 16) * APITCH + kk];
                a[mf][0] = __float_as_uint(ap[0]);
                a[mf][2] = __float_as_uint(ap[4]);
                a[mf][1] = __float_as_uint(ap[8 * APITCH]);
                a[mf][3] = __float_as_uint(ap[8 * APITCH + 4]);
            }
            uint32_t b[4][2];
            #pragma unroll
            for (int nf = 0; nf < 4; nf++) {
                const float* bp = &Ws[(brow + nf * 8) * APITCH + kk];
                b[nf][0] = __float_as_uint(bp[0]);
                b[nf][1] = __float_as_uint(bp[4]);
            }
            #pragma unroll
            for (int mf = 0; mf < 2; mf++)
                #pragma unroll
                for (int nf = 0; nf < 4; nf++)
                    mma8(d2[mf][nf], a[mf], b[nf]);
        }

        #pragma unroll
        for (int mf = 0; mf < 2; mf++) {
            #pragma unroll
            for (int half = 0; half < 2; half++) {
                int m = m0 + wm * 32 + mf * 16 + half * 8 + grp;
                if (m < M) {
                    #pragma unroll
                    for (int nf = 0; nf < 4; nf++) {
                        int ncol = wn * 32 + nf * 8 + tg * 2;
                        float2 v;
                        v.x = d2[mf][nf][half * 2 + 0] + bias2[ncol];
                        v.y = d2[mf][nf][half * 2 + 1] + bias2[ncol + 1];
                        *reinterpret_cast<float2*>(&out[(size_t)m * COUT + ncol]) = v;
                    }
                }
            }
        }
    }
}

// ---------------- launch ----------------
extern "C" void kernel_launch(void* const* d_in, const int* in_sizes, int n_in,
                              void* d_out, int out_size) {
    const float* x       = (const float*)d_in[0];
    const int*   ei      = (const int*)d_in[1];
    const float* ew      = (const float*)d_in[2];
    const float* w1      = (const float*)d_in[3];
    const float* b1      = (const float*)d_in[4];
    const float* bn1_g   = (const float*)d_in[5];
    const float* bn1_b   = (const float*)d_in[6];
    const float* bn1_m   = (const float*)d_in[7];
    const float* bn1_v   = (const float*)d_in[8];
    const float* conv_ws = (const float*)d_in[9];
    const float* conv_bs = (const float*)d_in[10];
    const float* bns_g   = (const float*)d_in[11];
    const float* bns_b   = (const float*)d_in[12];
    const float* bns_m   = (const float*)d_in[13];
    const float* bns_v   = (const float*)d_in[14];
    const float* lin1_w  = (const float*)d_in[15];
    const float* lin1_b  = (const float*)d_in[16];
    const float* lin2_w  = (const float*)d_in[17];
    const float* lin2_b  = (const float*)d_in[18];

    int n = in_sizes[0] / C;     // 50000
    int e = in_sizes[2];         // 800000
    const int* srcp = ei;
    const int* dstp = ei + e;

    const int SMEM_GEMM = 256 * APITCH * 4;   // 135168

    cudaFuncSetAttribute(gemm_bn_kernel<0>, cudaFuncAttributeMaxDynamicSharedMemorySize, SMEM_GEMM);
    cudaFuncSetAttribute(gemm_bn_kernel<1>, cudaFuncAttributeMaxDynamicSharedMemorySize, SMEM_GEMM);
    cudaFuncSetAttribute(tail_kernel,       cudaFuncAttributeMaxDynamicSharedMemorySize, SMEM_GEMM);

    float* wt = nullptr;   cudaGetSymbolAddress((void**)&wt, g_wt);
    float* bufA = nullptr; cudaGetSymbolAddress((void**)&bufA, g_bufA);
    float* bufB = nullptr; cudaGetSymbolAddress((void**)&bufB, g_bufB);

    int nb_e = (e + 255) / 256;

    count_tr_kernel<<<nb_e + (5 * 16384 - 8192 + 255) / 256, 256>>>(dstp, ew, e, w1, conv_ws, lin1_w, lin2_w);
    scan_kernel<<<NSCB, SCAN_B>>>(n, b1, bn1_g, bn1_b, bn1_m, bn1_v,
                                  conv_bs, bns_g, bns_b, bns_m, bns_v);
    fill_kernel<<<nb_e, 256>>>(srcp, dstp, ew, e);

    int ablocks = (n + 7) / 8;
    int gblocks = (n + 127) / 128;

    // layer 0                                  <- agg at ncu capture slot
    agg_kernel<<<ablocks, 256>>>(x, n);
    gemm_bn_kernel<0><<<gblocks, 256, SMEM_GEMM>>>(wt + 0 * 16384, 0, nullptr, bufA, n);

    // layer 1
    agg_kernel<<<ablocks, 256>>>(bufA, n);
    gemm_bn_kernel<1><<<gblocks, 256, SMEM_GEMM>>>(wt + 1 * 16384, 1, bufA, bufB, n);

    // layer 2 + heads fused (also restores zero invariants)
    agg_kernel<<<ablocks, 256>>>(bufB, n);
    tail_kernel<<<gblocks, 256, SMEM_GEMM>>>(bufB, wt + 2 * 16384, wt + 3 * 16384, lin1_b,
                                             wt + 4 * 16384, lin2_b, (float*)d_out, n);
}

// round 12
// speedup vs baseline: 1.4863x; 1.0395x over previous
#include <cuda_runtime.h>
#include <cuda_bf16.h>
#include <cstdint>

// Problem constants (fixed by the dataset)
#define NN   50000
#define EE   800000
#define C    128
#define COUT 64
#define EPSV 1e-5f
#define APITCH 132
#define SCAN_B 1024
#define NSCB   ((NN + SCAN_B - 1) / SCAN_B)   // 49

// ---------------- device scratch (no allocations allowed) ----------------
// Invariant: g_cnt, g_deg, g_bflag are ZERO at the start of every call.
// (zero at module load; tail_kernel re-zeroes all three at the end of each call.)
__device__ float g_deg[NN];
__device__ int   g_cnt[NN];
__device__ int   g_rowstart[NN + 1];
__device__ int   g_cursor[NN];
__device__ int   g_btot[NSCB];
__device__ int   g_bflag[NSCB];
__device__ int   g_col[EE];
__device__ float g_wv[EE];
__device__ float g_agg[(size_t)NN * C];
__device__ float g_bufA[(size_t)NN * C];
__device__ float g_bufB[(size_t)NN * C];
__device__ float g_bnA[3 * C];
__device__ float g_bnB[3 * C];
__device__ float g_wt[5 * 128 * 128];  // transposed weights WT[n][k], tf32-rounded

__device__ __forceinline__ float to_tf32(float f) {
    uint32_t u;
    asm("cvt.rna.tf32.f32 %0, %1;" : "=r"(u) : "f"(f));
    return __uint_as_float(u);
}

__device__ __forceinline__ void mma8(float* d, const uint32_t* a, const uint32_t* b) {
    asm volatile(
        "mma.sync.aligned.m16n8k8.row.col.f32.tf32.tf32.f32 "
        "{%0,%1,%2,%3}, {%4,%5,%6,%7}, {%8,%9}, {%0,%1,%2,%3};"
        : "+f"(d[0]), "+f"(d[1]), "+f"(d[2]), "+f"(d[3])
        : "r"(a[0]), "r"(a[1]), "r"(a[2]), "r"(a[3]), "r"(b[0]), "r"(b[1]));
}

// ---------------- stream A kernel 0: edge count/degree atomics ----------------
__global__ void count_kernel(const int* __restrict__ dst, const float* __restrict__ ew, int e) {
    int i = blockIdx.x * blockDim.x + threadIdx.x;
    if (i < e) {
        int d = dst[i];
        atomicAdd(&g_cnt[d], 1);
        atomicAdd(&g_deg[d], ew[i]);
    }
}

// ---------------- stream B kernel 0: weight transpose (tf32-rounded) ----------------
__global__ void tr_kernel(const float* __restrict__ w1, const float* __restrict__ conv_ws,
                          const float* __restrict__ lin1_w, const float* __restrict__ lin2_w) {
    int g = blockIdx.x * 256 + threadIdx.x;
    if (g < 4 * 16384) {
        int mat = g >> 14, idx = g & 16383;
        int k = idx >> 7, nn = idx & 127;
        const float* W = (mat == 0) ? w1 : ((mat == 3) ? lin1_w : (conv_ws + (mat - 1) * 16384));
        g_wt[mat * 16384 + nn * 128 + k] = to_tf32(W[k * 128 + nn]);
    } else if (g < 4 * 16384 + 8192) {
        int idx = g - 4 * 16384;
        int k = idx >> 6, nn = idx & 63;
        g_wt[4 * 16384 + nn * 128 + k] = to_tf32(lin2_w[k * 64 + nn]);
    }
}

// ---------------- single-pass scan (decoupled lookback) + dis + cursor + BN fold ----------------
__global__ __launch_bounds__(SCAN_B) void scan_kernel(int n, const float* b1,
                                  const float* g1, const float* be1, const float* m1, const float* v1,
                                  const float* conv_bs,
                                  const float* gs, const float* bes, const float* ms, const float* vs) {
    __shared__ int wsum[32];
    __shared__ int s_prefix;
    int t = threadIdx.x, lane = t & 31, w = t >> 5;
    int b = blockIdx.x;
    int i = b * SCAN_B + t;

    int v = (i < n) ? g_cnt[i] : 0;
    int x = v;
    #pragma unroll
    for (int o = 1; o < 32; o <<= 1) { int y = __shfl_up_sync(0xffffffffu, x, o); if (lane >= o) x += y; }
    if (lane == 31) wsum[w] = x;
    __syncthreads();
    if (w == 0) {
        int s = wsum[lane];
        #pragma unroll
        for (int o = 1; o < 32; o <<= 1) { int y = __shfl_up_sync(0xffffffffu, s, o); if (lane >= o) s += y; }
        wsum[lane] = s;
    }
    __syncthreads();
    int incl = x + (w > 0 ? wsum[w - 1] : 0);
    int btotal = wsum[31];

    if (t == 0) {
        atomicExch(&g_btot[b], btotal);
        __threadfence();
        atomicExch(&g_bflag[b], 1);
    }
    if (w == 1) {
        int sum = 0;
        for (int j = lane; j < b; j += 32) {
            while (atomicAdd(&g_bflag[j], 0) == 0) {}
            sum += atomicAdd(&g_btot[j], 0);
        }
        #pragma unroll
        for (int o = 16; o > 0; o >>= 1) sum += __shfl_down_sync(0xffffffffu, sum, o);
        if (lane == 0) s_prefix = sum;
    }
    __syncthreads();
    int prefix = s_prefix;

    if (i < n) {
        int rs = prefix + incl - v;
        g_rowstart[i] = rs;
        g_cursor[i] = rs;
        g_deg[i] = rsqrtf(g_deg[i] + 1.0f);   // + self loop
    }
    if (b == NSCB - 1 && t == 0) g_rowstart[n] = prefix + btotal;

    if (b == 0 && t < C) {
        int c = t;
        float sc = g1[c] * rsqrtf(v1[c] + EPSV);
        g_bnA[c] = sc;
        g_bnB[c] = be1[c] + (b1[c] - m1[c]) * sc;
        #pragma unroll
        for (int l = 0; l < 2; l++) {
            float s2 = gs[l * C + c] * rsqrtf(vs[l * C + c] + EPSV);
            g_bnA[(1 + l) * C + c] = s2;
            g_bnB[(1 + l) * C + c] = bes[l * C + c] + (conv_bs[l * C + c] - ms[l * C + c]) * s2;
        }
    }
}

// ---------------- CSR fill ----------------
__global__ void fill_kernel(const int* __restrict__ src, const int* __restrict__ dst,
                            const float* __restrict__ ew, int e) {
    int i = blockIdx.x * blockDim.x + threadIdx.x;
    if (i < e) {
        int s = src[i], d = dst[i];
        int pos = atomicAdd(&g_cursor[d], 1);
        g_col[pos] = s;
        g_wv[pos]  = g_deg[s] * ew[i] * g_deg[d];
    }
}

// ---------------- plain GEMM (no epilogue): out = tf32(X) @ W -> g_agg ----------------
__global__ __launch_bounds__(256) void gemm_plain_kernel(const float* __restrict__ X,
                                                         const float* __restrict__ WT, int M) {
    extern __shared__ float sm[];
    float* As = sm;                    // [128][APITCH]
    float* Ws = sm + 128 * APITCH;     // [128][APITCH]

    int tid = threadIdx.x;
    int wid = tid >> 5, lane = tid & 31;
    int m0 = blockIdx.x * 128;

    #pragma unroll
    for (int it = 0; it < 16; it++) {
        int idx = tid + it * 256;
        int r = idx >> 5, q = idx & 31;
        int m = m0 + r;
        float4 v = make_float4(0.f, 0.f, 0.f, 0.f);
        if (m < M) v = *reinterpret_cast<const float4*>(&X[(size_t)m * 128 + q * 4]);
        float* p = &As[r * APITCH + q * 4];
        p[0] = to_tf32(v.x); p[1] = to_tf32(v.y); p[2] = to_tf32(v.z); p[3] = to_tf32(v.w);
    }
    #pragma unroll
    for (int it = 0; it < 16; it++) {
        int idx = tid + it * 256;
        int r = idx >> 5, q = idx & 31;
        float4 v = *reinterpret_cast<const float4*>(&WT[(size_t)r * 128 + q * 4]);
        *reinterpret_cast<float4*>(&Ws[r * APITCH + q * 4]) = v;
    }
    __syncthreads();

    int wm = wid & 3, wn = wid >> 2;
    int grp = lane >> 2, tg = lane & 3;
    int arow = wm * 32 + grp;
    int brow = wn * 64 + grp;

    float d[2][8][4];
    #pragma unroll
    for (int i = 0; i < 2; i++)
        #pragma unroll
        for (int j = 0; j < 8; j++)
            #pragma unroll
            for (int q = 0; q < 4; q++) d[i][j][q] = 0.0f;

    #pragma unroll
    for (int k0 = 0; k0 < 16; k0++) {
        int kk = k0 * 8 + tg;
        uint32_t a[2][4];
        #pragma unroll
        for (int mf = 0; mf < 2; mf++) {
            const float* ap = &As[(arow + mf * 16) * APITCH + kk];
            a[mf][0] = __float_as_uint(ap[0]);
            a[mf][2] = __float_as_uint(ap[4]);
            a[mf][1] = __float_as_uint(ap[8 * APITCH]);
            a[mf][3] = __float_as_uint(ap[8 * APITCH + 4]);
        }
        uint32_t b[8][2];
        #pragma unroll
        for (int nf = 0; nf < 8; nf++) {
            const float* bp = &Ws[(brow + nf * 8) * APITCH + kk];
            b[nf][0] = __float_as_uint(bp[0]);
            b[nf][1] = __float_as_uint(bp[4]);
        }
        #pragma unroll
        for (int mf = 0; mf < 2; mf++)
            #pragma unroll
            for (int nf = 0; nf < 8; nf++)
                mma8(d[mf][nf], a[mf], b[nf]);
    }

    #pragma unroll
    for (int mf = 0; mf < 2; mf++) {
        #pragma unroll
        for (int half = 0; half < 2; half++) {
            int m = m0 + wm * 32 + mf * 16 + half * 8 + grp;
            if (m < M) {
                #pragma unroll
                for (int nf = 0; nf < 8; nf++) {
                    int ncol = wn * 64 + nf * 8 + tg * 2;
                    float2 v = make_float2(d[mf][nf][half * 2 + 0], d[mf][nf][half * 2 + 1]);
                    *reinterpret_cast<float2*>(&g_agg[(size_t)m * 128 + ncol]) = v;
                }
            }
        }
    }
}

// ---------------- layer-0 aggregation + BN + lrelu: bufA = lrelu(bn0(agg(tmp))) ----------------
__global__ __launch_bounds__(256) void agg_bn_kernel(int n) {
    int wid = threadIdx.x >> 5, lane = threadIdx.x & 31;
    int m = blockIdx.x * 8 + wid;
    if (m >= n) return;
    const float* H = g_agg;

    float dis = g_deg[m];
    float w0 = dis * dis;
    float4 h4 = *reinterpret_cast<const float4*>(&H[(size_t)m * 128 + lane * 4]);
    float4 acc = make_float4(w0 * h4.x, w0 * h4.y, w0 * h4.z, w0 * h4.w);

    int s = g_rowstart[m], e = g_rowstart[m + 1];
    int k = s;
    for (; k + 8 <= e; k += 8) {
        int   c0 = __ldg(&g_col[k]),     c1 = __ldg(&g_col[k + 1]);
        int   c2 = __ldg(&g_col[k + 2]), c3 = __ldg(&g_col[k + 3]);
        int   c4 = __ldg(&g_col[k + 4]), c5 = __ldg(&g_col[k + 5]);
        int   c6 = __ldg(&g_col[k + 6]), c7 = __ldg(&g_col[k + 7]);
        float w0e = __ldg(&g_wv[k]),     w1e = __ldg(&g_wv[k + 1]);
        float w2e = __ldg(&g_wv[k + 2]), w3e = __ldg(&g_wv[k + 3]);
        float w4e = __ldg(&g_wv[k + 4]), w5e = __ldg(&g_wv[k + 5]);
        float w6e = __ldg(&g_wv[k + 6]), w7e = __ldg(&g_wv[k + 7]);
        float4 v0 = *reinterpret_cast<const float4*>(&H[(size_t)c0 * 128 + lane * 4]);
        float4 v1 = *reinterpret_cast<const float4*>(&H[(size_t)c1 * 128 + lane * 4]);
        float4 v2 = *reinterpret_cast<const float4*>(&H[(size_t)c2 * 128 + lane * 4]);
        float4 v3 = *reinterpret_cast<const float4*>(&H[(size_t)c3 * 128 + lane * 4]);
        float4 v4 = *reinterpret_cast<const float4*>(&H[(size_t)c4 * 128 + lane * 4]);
        float4 v5 = *reinterpret_cast<const float4*>(&H[(size_t)c5 * 128 + lane * 4]);
        float4 v6 = *reinterpret_cast<const float4*>(&H[(size_t)c6 * 128 + lane * 4]);
        float4 v7 = *reinterpret_cast<const float4*>(&H[(size_t)c7 * 128 + lane * 4]);
        acc.x += w0e * v0.x + w1e * v1.x + w2e * v2.x + w3e * v3.x
               + w4e * v4.x + w5e * v5.x + w6e * v6.x + w7e * v7.x;
        acc.y += w0e * v0.y + w1e * v1.y + w2e * v2.y + w3e * v3.y
               + w4e * v4.y + w5e * v5.y + w6e * v6.y + w7e * v7.y;
        acc.z += w0e * v0.z + w1e * v1.z + w2e * v2.z + w3e * v3.z
               + w4e * v4.z + w5e * v5.z + w6e * v6.z + w7e * v7.z;
        acc.w += w0e * v0.w + w1e * v1.w + w2e * v2.w + w3e * v3.w
               + w4e * v4.w + w5e * v5.w + w6e * v6.w + w7e * v7.w;
    }
    for (; k < e; k++) {
        int cc = __ldg(&g_col[k]);
        float we = __ldg(&g_wv[k]);
        float4 v = *reinterpret_cast<const float4*>(&H[(size_t)cc * 128 + lane * 4]);
        acc.x += we * v.x; acc.y += we * v.y; acc.z += we * v.z; acc.w += we * v.w;
    }

    int c = lane * 4;
    float4 a4 = *reinterpret_cast<const float4*>(&g_bnA[c]);
    float4 b4 = *reinterpret_cast<const float4*>(&g_bnB[c]);
    float4 y;
    y.x = acc.x * a4.x + b4.x;  y.y = acc.y * a4.y + b4.y;
    y.z = acc.z * a4.z + b4.z;  y.w = acc.w * a4.w + b4.w;
    y.x = y.x > 0.f ? y.x : 0.01f * y.x;
    y.y = y.y > 0.f ? y.y : 0.01f * y.y;
    y.z = y.z > 0.f ? y.z : 0.01f * y.z;
    y.w = y.w > 0.f ? y.w : 0.01f * y.w;
    *reinterpret_cast<float4*>(&g_bufA[(size_t)m * 128 + c]) = y;
}

// ---------------- aggregation (layers 1,2): g_agg = agg(H) ----------------
__global__ __launch_bounds__(256) void agg_kernel(const float* __restrict__ H, int n) {
    int wid = threadIdx.x >> 5, lane = threadIdx.x & 31;
    int m = blockIdx.x * 8 + wid;
    if (m >= n) return;

    float dis = g_deg[m];
    float w0 = dis * dis;
    float4 h4 = *reinterpret_cast<const float4*>(&H[(size_t)m * 128 + lane * 4]);
    float4 acc = make_float4(w0 * h4.x, w0 * h4.y, w0 * h4.z, w0 * h4.w);

    int s = g_rowstart[m], e = g_rowstart[m + 1];
    int k = s;
    for (; k + 8 <= e; k += 8) {
        int   c0 = __ldg(&g_col[k]),     c1 = __ldg(&g_col[k + 1]);
        int   c2 = __ldg(&g_col[k + 2]), c3 = __ldg(&g_col[k + 3]);
        int   c4 = __ldg(&g_col[k + 4]), c5 = __ldg(&g_col[k + 5]);
        int   c6 = __ldg(&g_col[k + 6]), c7 = __ldg(&g_col[k + 7]);
        float w0e = __ldg(&g_wv[k]),     w1e = __ldg(&g_wv[k + 1]);
        float w2e = __ldg(&g_wv[k + 2]), w3e = __ldg(&g_wv[k + 3]);
        float w4e = __ldg(&g_wv[k + 4]), w5e = __ldg(&g_wv[k + 5]);
        float w6e = __ldg(&g_wv[k + 6]), w7e = __ldg(&g_wv[k + 7]);
        float4 v0 = *reinterpret_cast<const float4*>(&H[(size_t)c0 * 128 + lane * 4]);
        float4 v1 = *reinterpret_cast<const float4*>(&H[(size_t)c1 * 128 + lane * 4]);
        float4 v2 = *reinterpret_cast<const float4*>(&H[(size_t)c2 * 128 + lane * 4]);
        float4 v3 = *reinterpret_cast<const float4*>(&H[(size_t)c3 * 128 + lane * 4]);
        float4 v4 = *reinterpret_cast<const float4*>(&H[(size_t)c4 * 128 + lane * 4]);
        float4 v5 = *reinterpret_cast<const float4*>(&H[(size_t)c5 * 128 + lane * 4]);
        float4 v6 = *reinterpret_cast<const float4*>(&H[(size_t)c6 * 128 + lane * 4]);
        float4 v7 = *reinterpret_cast<const float4*>(&H[(size_t)c7 * 128 + lane * 4]);
        acc.x += w0e * v0.x + w1e * v1.x + w2e * v2.x + w3e * v3.x
               + w4e * v4.x + w5e * v5.x + w6e * v6.x + w7e * v7.x;
        acc.y += w0e * v0.y + w1e * v1.y + w2e * v2.y + w3e * v3.y
               + w4e * v4.y + w5e * v5.y + w6e * v6.y + w7e * v7.y;
        acc.z += w0e * v0.z + w1e * v1.z + w2e * v2.z + w3e * v3.z
               + w4e * v4.z + w5e * v5.z + w6e * v6.z + w7e * v7.z;
        acc.w += w0e * v0.w + w1e * v1.w + w2e * v2.w + w3e * v3.w
               + w4e * v4.w + w5e * v5.w + w6e * v6.w + w7e * v7.w;
    }
    for (; k < e; k++) {
        int cc = __ldg(&g_col[k]);
        float we = __ldg(&g_wv[k]);
        float4 v = *reinterpret_cast<const float4*>(&H[(size_t)cc * 128 + lane * 4]);
        acc.x += we * v.x; acc.y += we * v.y; acc.z += we * v.z; acc.w += we * v.w;
    }
    *reinterpret_cast<float4*>(&g_agg[(size_t)m * 128 + lane * 4]) = acc;
}

// ---------------- GEMM + BN + residual + lrelu (layer 1) ----------------
template <int HASRES>
__global__ __launch_bounds__(256) void gemm_bn_kernel(const float* __restrict__ WT,
                                                      int layer, const float* __restrict__ H,
                                                      float* __restrict__ out, int M) {
    extern __shared__ float sm[];
    float* As = sm;
    float* Ws = sm + 128 * APITCH;

    int tid = threadIdx.x;
    int wid = tid >> 5, lane = tid & 31;
    int m0 = blockIdx.x * 128;

    #pragma unroll
    for (int it = 0; it < 16; it++) {
        int idx = tid + it * 256;
        int r = idx >> 5, q = idx & 31;
        int m = m0 + r;
        float4 v = make_float4(0.f, 0.f, 0.f, 0.f);
        if (m < M) v = *reinterpret_cast<const float4*>(&g_agg[(size_t)m * 128 + q * 4]);
        float* p = &As[r * APITCH + q * 4];
        p[0] = to_tf32(v.x); p[1] = to_tf32(v.y); p[2] = to_tf32(v.z); p[3] = to_tf32(v.w);
    }
    #pragma unroll
    for (int it = 0; it < 16; it++) {
        int idx = tid + it * 256;
        int r = idx >> 5, q = idx & 31;
        float4 v = *reinterpret_cast<const float4*>(&WT[(size_t)r * 128 + q * 4]);
        *reinterpret_cast<float4*>(&Ws[r * APITCH + q * 4]) = v;
    }
    __syncthreads();

    int wm = wid & 3, wn = wid >> 2;
    int grp = lane >> 2, tg = lane & 3;
    int arow = wm * 32 + grp;
    int brow = wn * 64 + grp;

    float d[2][8][4];
    #pragma unroll
    for (int i = 0; i < 2; i++)
        #pragma unroll
        for (int j = 0; j < 8; j++)
            #pragma unroll
            for (int q = 0; q < 4; q++) d[i][j][q] = 0.0f;

    #pragma unroll
    for (int k0 = 0; k0 < 16; k0++) {
        int kk = k0 * 8 + tg;
        uint32_t a[2][4];
        #pragma unroll
        for (int mf = 0; mf < 2; mf++) {
            const float* ap = &As[(arow + mf * 16) * APITCH + kk];
            a[mf][0] = __float_as_uint(ap[0]);
            a[mf][2] = __float_as_uint(ap[4]);
            a[mf][1] = __float_as_uint(ap[8 * APITCH]);
            a[mf][3] = __float_as_uint(ap[8 * APITCH + 4]);
        }
        uint32_t b[8][2];
        #pragma unroll
        for (int nf = 0; nf < 8; nf++) {
            const float* bp = &Ws[(brow + nf * 8) * APITCH + kk];
            b[nf][0] = __float_as_uint(bp[0]);
            b[nf][1] = __float_as_uint(bp[4]);
        }
        #pragma unroll
        for (int mf = 0; mf < 2; mf++)
            #pragma unroll
            for (int nf = 0; nf < 8; nf++)
                mma8(d[mf][nf], a[mf], b[nf]);
    }

    const float* bnA = &g_bnA[layer * C];
    const float* bnB = &g_bnB[layer * C];
    #pragma unroll
    for (int mf = 0; mf < 2; mf++) {
        #pragma unroll
        for (int half = 0; half < 2; half++) {
            int m = m0 + wm * 32 + mf * 16 + half * 8 + grp;
            if (m < M) {
                #pragma unroll
                for (int nf = 0; nf < 8; nf++) {
                    int ncol = wn * 64 + nf * 8 + tg * 2;
                    float2 v;
                    v.x = d[mf][nf][half * 2 + 0] * bnA[ncol]     + bnB[ncol];
                    v.y = d[mf][nf][half * 2 + 1] * bnA[ncol + 1] + bnB[ncol + 1];
                    if (HASRES) {
                        float2 rv = *reinterpret_cast<const float2*>(&H[(size_t)m * 128 + ncol]);
                        v.x += rv.x; v.y += rv.y;
                    }
                    v.x = v.x > 0.f ? v.x : 0.01f * v.x;
                    v.y = v.y > 0.f ? v.y : 0.01f * v.y;
                    *reinterpret_cast<float2*>(&out[(size_t)m * 128 + ncol]) = v;
                }
            }
        }
    }
}

// ---------------- fused tail: layer-2 GEMM+BN+res+lrelu -> lin1+lrelu -> lin2 -> out ----------------
__global__ __launch_bounds__(256) void tail_kernel(const float* __restrict__ H,
                                                   const float* __restrict__ WcT,
                                                   const float* __restrict__ WT1,
                                                   const float* __restrict__ bias1,
                                                   const float* __restrict__ WT2,
                                                   const float* __restrict__ bias2,
                                                   float* __restrict__ out, int M) {
    extern __shared__ float sm[];
    float* As = sm;
    float* Ws = sm + 128 * APITCH;

    int tid = threadIdx.x;
    int wid = tid >> 5, lane = tid & 31;
    int m0 = blockIdx.x * 128;

    {
        int z = blockIdx.x * 256 + tid;
        if (z < NN) { g_deg[z] = 0.0f; g_cnt[z] = 0; }
        if (z < NSCB) g_bflag[z] = 0;
    }

    int wm = wid & 3, wn = wid >> 2;
    int grp = lane >> 2, tg = lane & 3;
    int arow = wm * 32 + grp;

    #pragma unroll
    for (int it = 0; it < 16; it++) {
        int idx = tid + it * 256;
        int r = idx >> 5, q = idx & 31;
        int m = m0 + r;
        float4 v = make_float4(0.f, 0.f, 0.f, 0.f);
        if (m < M) v = *reinterpret_cast<const float4*>(&g_agg[(size_t)m * 128 + q * 4]);
        float* p = &As[r * APITCH + q * 4];
        p[0] = to_tf32(v.x); p[1] = to_tf32(v.y); p[2] = to_tf32(v.z); p[3] = to_tf32(v.w);
    }
    #pragma unroll
    for (int it = 0; it < 16; it++) {
        int idx = tid + it * 256;
        int r = idx >> 5, q = idx & 31;
        float4 v = *reinterpret_cast<const float4*>(&WcT[(size_t)r * 128 + q * 4]);
        *reinterpret_cast<float4*>(&Ws[r * APITCH + q * 4]) = v;
    }
    __syncthreads();

    float d[2][8][4];

    // ---- stage 0: layer-2 GEMM ----
    {
        int brow = wn * 64 + grp;
        #pragma unroll
        for (int i = 0; i < 2; i++)
            #pragma unroll
            for (int j = 0; j < 8; j++)
                #pragma unroll
                for (int q = 0; q < 4; q++) d[i][j][q] = 0.0f;
        #pragma unroll
        for (int k0 = 0; k0 < 16; k0++) {
            int kk = k0 * 8 + tg;
            uint32_t a[2][4];
            #pragma unroll
            for (int mf = 0; mf < 2; mf++) {
                const float* ap = &As[(arow + mf * 16) * APITCH + kk];
                a[mf][0] = __float_as_uint(ap[0]);
                a[mf][2] = __float_as_uint(ap[4]);
                a[mf][1] = __float_as_uint(ap[8 * APITCH]);
                a[mf][3] = __float_as_uint(ap[8 * APITCH + 4]);
            }
            uint32_t b[8][2];
            #pragma unroll
            for (int nf = 0; nf < 8; nf++) {
                const float* bp = &Ws[(brow + nf * 8) * APITCH + kk];
                b[nf][0] = __float_as_uint(bp[0]);
                b[nf][1] = __float_as_uint(bp[4]);
            }
            #pragma unroll
            for (int mf = 0; mf < 2; mf++)
                #pragma unroll
                for (int nf = 0; nf < 8; nf++)
                    mma8(d[mf][nf], a[mf], b[nf]);
        }
    }
    __syncthreads();

    // z0 = lrelu(bn2(d) + residual) -> As ; stage Ws = lin1
    {
        const float* bnA = &g_bnA[2 * C];
        const float* bnB = &g_bnB[2 * C];
        #pragma unroll
        for (int mf = 0; mf < 2; mf++) {
            #pragma unroll
            for (int half = 0; half < 2; half++) {
                int r = wm * 32 + mf * 16 + half * 8 + grp;
                int m = m0 + r;
                #pragma unroll
                for (int nf = 0; nf < 8; nf++) {
                    int ncol = wn * 64 + nf * 8 + tg * 2;
                    float vx = d[mf][nf][half * 2 + 0] * bnA[ncol]     + bnB[ncol];
                    float vy = d[mf][nf][half * 2 + 1] * bnA[ncol + 1] + bnB[ncol + 1];
                    if (m < M) {
                        float2 rv = *reinterpret_cast<const float2*>(&H[(size_t)m * 128 + ncol]);
                        vx += rv.x; vy += rv.y;
                    }
                    vx = vx > 0.f ? vx : 0.01f * vx;
                    vy = vy > 0.f ? vy : 0.01f * vy;
                    As[r * APITCH + ncol]     = to_tf32(vx);
                    As[r * APITCH + ncol + 1] = to_tf32(vy);
                }
            }
        }
        #pragma unroll
        for (int it = 0; it < 16; it++) {
            int idx = tid + it * 256;
            int r = idx >> 5, q = idx & 31;
            float4 v = *reinterpret_cast<const float4*>(&WT1[(size_t)r * 128 + q * 4]);
            *reinterpret_cast<float4*>(&Ws[r * APITCH + q * 4]) = v;
        }
    }
    __syncthreads();

    // ---- stage 1: lin1 ----
    {
        int brow = wn * 64 + grp;
        #pragma unroll
        for (int i = 0; i < 2; i++)
            #pragma unroll
            for (int j = 0; j < 8; j++)
                #pragma unroll
                for (int q = 0; q < 4; q++) d[i][j][q] = 0.0f;
        #pragma unroll
        for (int k0 = 0; k0 < 16; k0++) {
            int kk = k0 * 8 + tg;
            uint32_t a[2][4];
            #pragma unroll
            for (int mf = 0; mf < 2; mf++) {
                const float* ap = &As[(arow + mf * 16) * APITCH + kk];
                a[mf][0] = __float_as_uint(ap[0]);
                a[mf][2] = __float_as_uint(ap[4]);
                a[mf][1] = __float_as_uint(ap[8 * APITCH]);
                a[mf][3] = __float_as_uint(ap[8 * APITCH + 4]);
            }
            uint32_t b[8][2];
            #pragma unroll
            for (int nf = 0; nf < 8; nf++) {
                const float* bp = &Ws[(brow + nf * 8) * APITCH + kk];
                b[nf][0] = __float_as_uint(bp[0]);
                b[nf][1] = __float_as_uint(bp[4]);
            }
            #pragma unroll
            for (int mf = 0; mf < 2; mf++)
                #pragma unroll
                for (int nf = 0; nf < 8; nf++)
                    mma8(d[mf][nf], a[mf], b[nf]);
        }
    }
    __syncthreads();

    // z1 = lrelu(d + bias1) -> As ; stage Ws = lin2
    {
        #pragma unroll
        for (int mf = 0; mf < 2; mf++) {
            #pragma unroll
            for (int half = 0; half < 2; half++) {
                int r = wm * 32 + mf * 16 + half * 8 + grp;
                #pragma unroll
                for (int nf = 0; nf < 8; nf++) {
                    int ncol = wn * 64 + nf * 8 + tg * 2;
                    float vx = d[mf][nf][half * 2 + 0] + bias1[ncol];
                    float vy = d[mf][nf][half * 2 + 1] + bias1[ncol + 1];
                    vx = vx > 0.f ? vx : 0.01f * vx;
                    vy = vy > 0.f ? vy : 0.01f * vy;
                    As[r * APITCH + ncol]     = to_tf32(vx);
                    As[r * APITCH + ncol + 1] = to_tf32(vy);
                }
            }
        }
        #pragma unroll
        for (int it = 0; it < 8; it++) {
            int idx = tid + it * 256;
            int r = idx >> 5, q = idx & 31;
            float4 v = *reinterpret_cast<const float4*>(&WT2[(size_t)r * 128 + q * 4]);
            *reinterpret_cast<float4*>(&Ws[r * APITCH + q * 4]) = v;
        }
    }
    __syncthreads();

    // ---- stage 2: lin2 -> gmem ----
    {
        int brow = wn * 32 + grp;
        float d2[2][4][4];
        #pragma unroll
        for (int i = 0; i < 2; i++)
            #pragma unroll
            for (int j = 0; j < 4; j++)
                #pragma unroll
                for (int q = 0; q < 4; q++) d2[i][j][q] = 0.0f;
        #pragma unroll
        for (int k0 = 0; k0 < 16; k0++) {
            int kk = k0 * 8 + tg;
            uint32_t a[2][4];
            #pragma unroll
            for (int mf = 0; mf < 2; mf++) {
                const float* ap = &As[(arow + mf * 16) * APITCH + kk];
                a[mf][0] = __float_as_uint(ap[0]);
                a[mf][2] = __float_as_uint(ap[4]);
                a[mf][1] = __float_as_uint(ap[8 * APITCH]);
                a[mf][3] = __float_as_uint(ap[8 * APITCH + 4]);
            }
            uint32_t b[4][2];
            #pragma unroll
            for (int nf = 0; nf < 4; nf++) {
                const float* bp = &Ws[(brow + nf * 8) * APITCH + kk];
                b[nf][0] = __float_as_uint(bp[0]);
                b[nf][1] = __float_as_uint(bp[4]);
            }
            #pragma unroll
            for (int mf = 0; mf < 2; mf++)
                #pragma unroll
                for (int nf = 0; nf < 4; nf++)
                    mma8(d2[mf][nf], a[mf], b[nf]);
        }

        #pragma unroll
        for (int mf = 0; mf < 2; mf++) {
            #pragma unroll
            for (int half = 0; half < 2; half++) {
                int m = m0 + wm * 32 + mf * 16 + half * 8 + grp;
                if (m < M) {
                    #pragma unroll
                    for (int nf = 0; nf < 4; nf++) {
                        int ncol = wn * 32 + nf * 8 + tg * 2;
                        float2 v;
                        v.x = d2[mf][nf][half * 2 + 0] + bias2[ncol];
                        v.y = d2[mf][nf][half * 2 + 1] + bias2[ncol + 1];
                        *reinterpret_cast<float2*>(&out[(size_t)m * COUT + ncol]) = v;
                    }
                }
            }
        }
    }
}

// ---------------- launch ----------------
extern "C" void kernel_launch(void* const* d_in, const int* in_sizes, int n_in,
                              void* d_out, int out_size) {
    const float* x       = (const float*)d_in[0];
    const int*   ei      = (const int*)d_in[1];
    const float* ew      = (const float*)d_in[2];
    const float* w1      = (const float*)d_in[3];
    const float* b1      = (const float*)d_in[4];
    const float* bn1_g   = (const float*)d_in[5];
    const float* bn1_b   = (const float*)d_in[6];
    const float* bn1_m   = (const float*)d_in[7];
    const float* bn1_v   = (const float*)d_in[8];
    const float* conv_ws = (const float*)d_in[9];
    const float* conv_bs = (const float*)d_in[10];
    const float* bns_g   = (const float*)d_in[11];
    const float* bns_b   = (const float*)d_in[12];
    const float* bns_m   = (const float*)d_in[13];
    const float* bns_v   = (const float*)d_in[14];
    const float* lin1_w  = (const float*)d_in[15];
    const float* lin1_b  = (const float*)d_in[16];
    const float* lin2_w  = (const float*)d_in[17];
    const float* lin2_b  = (const float*)d_in[18];

    int n = in_sizes[0] / C;     // 50000
    int e = in_sizes[2];         // 800000
    const int* srcp = ei;
    const int* dstp = ei + e;

    const int SMEM_GEMM = 256 * APITCH * 4;   // 135168

    cudaFuncSetAttribute(gemm_plain_kernel, cudaFuncAttributeMaxDynamicSharedMemorySize, SMEM_GEMM);
    cudaFuncSetAttribute(gemm_bn_kernel<1>, cudaFuncAttributeMaxDynamicSharedMemorySize, SMEM_GEMM);
    cudaFuncSetAttribute(tail_kernel,       cudaFuncAttributeMaxDynamicSharedMemorySize, SMEM_GEMM);

    float* wt = nullptr;   cudaGetSymbolAddress((void**)&wt, g_wt);
    float* bufA = nullptr; cudaGetSymbolAddress((void**)&bufA, g_bufA);
    float* bufB = nullptr; cudaGetSymbolAddress((void**)&bufB, g_bufB);

    // side stream + fork/join events (created on first call, which is the
    // non-captured correctness run; reused across graph captures)
    static cudaStream_t sB = nullptr;
    static cudaEvent_t evFork = nullptr, evJoin = nullptr;
    if (!sB) {
        cudaStreamCreateWithFlags(&sB, cudaStreamNonBlocking);
        cudaEventCreateWithFlags(&evFork, cudaEventDisableTiming);
        cudaEventCreateWithFlags(&evJoin, cudaEventDisableTiming);
    }

    int nb_e = (e + 255) / 256;
    int ablocks = (n + 7) / 8;
    int gblocks = (n + 127) / 128;

    // fork: stream B does weight transpose + layer-0 GEMM (graph-independent)
    cudaEventRecord(evFork, 0);
    cudaStreamWaitEvent(sB, evFork, 0);

    // stream A (default): graph preprocessing
    count_kernel<<<nb_e, 256>>>(dstp, ew, e);
    scan_kernel<<<NSCB, SCAN_B>>>(n, b1, bn1_g, bn1_b, bn1_m, bn1_v,
                                  conv_bs, bns_g, bns_b, bns_m, bns_v);
    fill_kernel<<<nb_e, 256>>>(srcp, dstp, ew, e);

    // stream B: transpose weights, then tmp = x @ w1 -> g_agg
    tr_kernel<<<(5 * 16384 - 8192 + 255) / 256, 256, 0, sB>>>(w1, conv_ws, lin1_w, lin2_w);
    gemm_plain_kernel<<<gblocks, 256, SMEM_GEMM, sB>>>(x, wt + 0 * 16384, n);

    // join
    cudaEventRecord(evJoin, sB);
    cudaStreamWaitEvent(0, evJoin, 0);

    // layer 0: bufA = lrelu(bn0(agg(tmp)))
    agg_bn_kernel<<<ablocks, 256>>>(n);

    // layer 1
    agg_kernel<<<ablocks, 256>>>(bufA, n);
    gemm_bn_kernel<1><<<gblocks, 256, SMEM_GEMM>>>(wt + 1 * 16384, 1, bufA, bufB, n);

    // layer 2 + heads fused (also restores zero invariants)
    agg_kernel<<<ablocks, 256>>>(bufB, n);
    tail_kernel<<<gblocks, 256, SMEM_GEMM>>>(bufB, wt + 2 * 16384, wt + 3 * 16384, lin1_b,
                                             wt + 4 * 16384, lin2_b, (float*)d_out, n);
}

// round 13
// speedup vs baseline: 1.4910x; 1.0031x over previous
#include <cuda_runtime.h>
#include <cuda_bf16.h>
#include <cstdint>

// Problem constants (fixed by the dataset)
#define NN   50000
#define EE   800000
#define C    128
#define COUT 64
#define EPSV 1e-5f
#define APITCH 132
#define SCAN_B 1024
#define NSCB   ((NN + SCAN_B - 1) / SCAN_B)   // 49

// ---------------- device scratch (no allocations allowed) ----------------
// Invariant: g_cnt, g_deg, g_bflag are ZERO at the start of every call.
// (zero at module load; tail_kernel re-zeroes all three at the end of each call.)
__device__ float g_deg[NN];
__device__ int   g_cnt[NN];
__device__ int   g_rowstart[NN + 1];
__device__ int   g_rank[EE];           // per-edge rank within its dst row
__device__ int   g_btot[NSCB];
__device__ int   g_bflag[NSCB];
__device__ int   g_col[EE];
__device__ float g_wv[EE];
__device__ float g_agg[(size_t)NN * C];
__device__ float g_bufA[(size_t)NN * C];
__device__ float g_bufB[(size_t)NN * C];
__device__ float g_bnA[3 * C];
__device__ float g_bnB[3 * C];
__device__ float g_wt[5 * 128 * 128];  // transposed weights WT[n][k], tf32-rounded

__device__ __forceinline__ float to_tf32(float f) {
    uint32_t u;
    asm("cvt.rna.tf32.f32 %0, %1;" : "=r"(u) : "f"(f));
    return __uint_as_float(u);
}

__device__ __forceinline__ void mma8(float* d, const uint32_t* a, const uint32_t* b) {
    asm volatile(
        "mma.sync.aligned.m16n8k8.row.col.f32.tf32.tf32.f32 "
        "{%0,%1,%2,%3}, {%4,%5,%6,%7}, {%8,%9}, {%0,%1,%2,%3};"
        : "+f"(d[0]), "+f"(d[1]), "+f"(d[2]), "+f"(d[3])
        : "r"(a[0]), "r"(a[1]), "r"(a[2]), "r"(a[3]), "r"(b[0]), "r"(b[1]));
}

// ---------------- stream A kernel 0: edge count/degree atomics + rank recording ----------------
__global__ void count_kernel(const int* __restrict__ dst, const float* __restrict__ ew, int e) {
    int i = blockIdx.x * blockDim.x + threadIdx.x;
    if (i < e) {
        int d = dst[i];
        g_rank[i] = atomicAdd(&g_cnt[d], 1);
        atomicAdd(&g_deg[d], ew[i]);
    }
}

// ---------------- stream B kernel 0: weight transpose (tf32-rounded) ----------------
__global__ void tr_kernel(const float* __restrict__ w1, const float* __restrict__ conv_ws,
                          const float* __restrict__ lin1_w, const float* __restrict__ lin2_w) {
    int g = blockIdx.x * 256 + threadIdx.x;
    if (g < 4 * 16384) {
        int mat = g >> 14, idx = g & 16383;
        int k = idx >> 7, nn = idx & 127;
        const float* W = (mat == 0) ? w1 : ((mat == 3) ? lin1_w : (conv_ws + (mat - 1) * 16384));
        g_wt[mat * 16384 + nn * 128 + k] = to_tf32(W[k * 128 + nn]);
    } else if (g < 4 * 16384 + 8192) {
        int idx = g - 4 * 16384;
        int k = idx >> 6, nn = idx & 63;
        g_wt[4 * 16384 + nn * 128 + k] = to_tf32(lin2_w[k * 64 + nn]);
    }
}

// ---------------- single-pass scan (decoupled lookback) + dis + BN fold ----------------
__global__ __launch_bounds__(SCAN_B) void scan_kernel(int n, const float* b1,
                                  const float* g1, const float* be1, const float* m1, const float* v1,
                                  const float* conv_bs,
                                  const float* gs, const float* bes, const float* ms, const float* vs) {
    __shared__ int wsum[32];
    __shared__ int s_prefix;
    int t = threadIdx.x, lane = t & 31, w = t >> 5;
    int b = blockIdx.x;
    int i = b * SCAN_B + t;

    int v = (i < n) ? g_cnt[i] : 0;
    int x = v;
    #pragma unroll
    for (int o = 1; o < 32; o <<= 1) { int y = __shfl_up_sync(0xffffffffu, x, o); if (lane >= o) x += y; }
    if (lane == 31) wsum[w] = x;
    __syncthreads();
    if (w == 0) {
        int s = wsum[lane];
        #pragma unroll
        for (int o = 1; o < 32; o <<= 1) { int y = __shfl_up_sync(0xffffffffu, s, o); if (lane >= o) s += y; }
        wsum[lane] = s;
    }
    __syncthreads();
    int incl = x + (w > 0 ? wsum[w - 1] : 0);
    int btotal = wsum[31];

    if (t == 0) {
        atomicExch(&g_btot[b], btotal);
        __threadfence();
        atomicExch(&g_bflag[b], 1);
    }
    if (w == 1) {
        int sum = 0;
        for (int j = lane; j < b; j += 32) {
            while (atomicAdd(&g_bflag[j], 0) == 0) {}
            sum += atomicAdd(&g_btot[j], 0);
        }
        #pragma unroll
        for (int o = 16; o > 0; o >>= 1) sum += __shfl_down_sync(0xffffffffu, sum, o);
        if (lane == 0) s_prefix = sum;
    }
    __syncthreads();
    int prefix = s_prefix;

    if (i < n) {
        g_rowstart[i] = prefix + incl - v;
        g_deg[i] = rsqrtf(g_deg[i] + 1.0f);   // + self loop
    }
    if (b == NSCB - 1 && t == 0) g_rowstart[n] = prefix + btotal;

    if (b == 0 && t < C) {
        int c = t;
        float sc = g1[c] * rsqrtf(v1[c] + EPSV);
        g_bnA[c] = sc;
        g_bnB[c] = be1[c] + (b1[c] - m1[c]) * sc;
        #pragma unroll
        for (int l = 0; l < 2; l++) {
            float s2 = gs[l * C + c] * rsqrtf(vs[l * C + c] + EPSV);
            g_bnA[(1 + l) * C + c] = s2;
            g_bnB[(1 + l) * C + c] = bes[l * C + c] + (conv_bs[l * C + c] - ms[l * C + c]) * s2;
        }
    }
}

// ---------------- CSR fill: atomic-free (pos = rowstart[dst] + rank) ----------------
__global__ void fill_kernel(const int* __restrict__ src, const int* __restrict__ dst,
                            const float* __restrict__ ew, int lo, int hi) {
    int i = lo + blockIdx.x * blockDim.x + threadIdx.x;
    if (i < hi) {
        int s = src[i], d = dst[i];
        int pos = g_rowstart[d] + g_rank[i];
        g_col[pos] = s;
        g_wv[pos]  = g_deg[s] * ew[i] * g_deg[d];
    }
}

// ---------------- plain GEMM (no epilogue): g_agg = tf32(X) @ W ----------------
__global__ __launch_bounds__(256) void gemm_plain_kernel(const float* __restrict__ X,
                                                         const float* __restrict__ WT, int M) {
    extern __shared__ float sm[];
    float* As = sm;
    float* Ws = sm + 128 * APITCH;

    int tid = threadIdx.x;
    int wid = tid >> 5, lane = tid & 31;
    int m0 = blockIdx.x * 128;

    #pragma unroll
    for (int it = 0; it < 16; it++) {
        int idx = tid + it * 256;
        int r = idx >> 5, q = idx & 31;
        int m = m0 + r;
        float4 v = make_float4(0.f, 0.f, 0.f, 0.f);
        if (m < M) v = *reinterpret_cast<const float4*>(&X[(size_t)m * 128 + q * 4]);
        float* p = &As[r * APITCH + q * 4];
        p[0] = to_tf32(v.x); p[1] = to_tf32(v.y); p[2] = to_tf32(v.z); p[3] = to_tf32(v.w);
    }
    #pragma unroll
    for (int it = 0; it < 16; it++) {
        int idx = tid + it * 256;
        int r = idx >> 5, q = idx & 31;
        float4 v = *reinterpret_cast<const float4*>(&WT[(size_t)r * 128 + q * 4]);
        *reinterpret_cast<float4*>(&Ws[r * APITCH + q * 4]) = v;
    }
    __syncthreads();

    int wm = wid & 3, wn = wid >> 2;
    int grp = lane >> 2, tg = lane & 3;
    int arow = wm * 32 + grp;
    int brow = wn * 64 + grp;

    float d[2][8][4];
    #pragma unroll
    for (int i = 0; i < 2; i++)
        #pragma unroll
        for (int j = 0; j < 8; j++)
            #pragma unroll
            for (int q = 0; q < 4; q++) d[i][j][q] = 0.0f;

    #pragma unroll
    for (int k0 = 0; k0 < 16; k0++) {
        int kk = k0 * 8 + tg;
        uint32_t a[2][4];
        #pragma unroll
        for (int mf = 0; mf < 2; mf++) {
            const float* ap = &As[(arow + mf * 16) * APITCH + kk];
            a[mf][0] = __float_as_uint(ap[0]);
            a[mf][2] = __float_as_uint(ap[4]);
            a[mf][1] = __float_as_uint(ap[8 * APITCH]);
            a[mf][3] = __float_as_uint(ap[8 * APITCH + 4]);
        }
        uint32_t b[8][2];
        #pragma unroll
        for (int nf = 0; nf < 8; nf++) {
            const float* bp = &Ws[(brow + nf * 8) * APITCH + kk];
            b[nf][0] = __float_as_uint(bp[0]);
            b[nf][1] = __float_as_uint(bp[4]);
        }
        #pragma unroll
        for (int mf = 0; mf < 2; mf++)
            #pragma unroll
            for (int nf = 0; nf < 8; nf++)
                mma8(d[mf][nf], a[mf], b[nf]);
    }

    #pragma unroll
    for (int mf = 0; mf < 2; mf++) {
        #pragma unroll
        for (int half = 0; half < 2; half++) {
            int m = m0 + wm * 32 + mf * 16 + half * 8 + grp;
            if (m < M) {
                #pragma unroll
                for (int nf = 0; nf < 8; nf++) {
                    int ncol = wn * 64 + nf * 8 + tg * 2;
                    float2 v = make_float2(d[mf][nf][half * 2 + 0], d[mf][nf][half * 2 + 1]);
                    *reinterpret_cast<float2*>(&g_agg[(size_t)m * 128 + ncol]) = v;
                }
            }
        }
    }
}

// ---------------- layer-0 aggregation + BN + lrelu: bufA = lrelu(bn0(agg(tmp))) ----------------
__global__ __launch_bounds__(256) void agg_bn_kernel(int n) {
    int wid = threadIdx.x >> 5, lane = threadIdx.x & 31;
    int m = blockIdx.x * 8 + wid;
    if (m >= n) return;
    const float* H = g_agg;

    float dis = g_deg[m];
    float w0 = dis * dis;
    float4 h4 = *reinterpret_cast<const float4*>(&H[(size_t)m * 128 + lane * 4]);
    float4 acc = make_float4(w0 * h4.x, w0 * h4.y, w0 * h4.z, w0 * h4.w);

    int s = g_rowstart[m], e = g_rowstart[m + 1];
    int k = s;
    for (; k + 8 <= e; k += 8) {
        int   c0 = __ldg(&g_col[k]),     c1 = __ldg(&g_col[k + 1]);
        int   c2 = __ldg(&g_col[k + 2]), c3 = __ldg(&g_col[k + 3]);
        int   c4 = __ldg(&g_col[k + 4]), c5 = __ldg(&g_col[k + 5]);
        int   c6 = __ldg(&g_col[k + 6]), c7 = __ldg(&g_col[k + 7]);
        float w0e = __ldg(&g_wv[k]),     w1e = __ldg(&g_wv[k + 1]);
        float w2e = __ldg(&g_wv[k + 2]), w3e = __ldg(&g_wv[k + 3]);
        float w4e = __ldg(&g_wv[k + 4]), w5e = __ldg(&g_wv[k + 5]);
        float w6e = __ldg(&g_wv[k + 6]), w7e = __ldg(&g_wv[k + 7]);
        float4 v0 = *reinterpret_cast<const float4*>(&H[(size_t)c0 * 128 + lane * 4]);
        float4 v1 = *reinterpret_cast<const float4*>(&H[(size_t)c1 * 128 + lane * 4]);
        float4 v2 = *reinterpret_cast<const float4*>(&H[(size_t)c2 * 128 + lane * 4]);
        float4 v3 = *reinterpret_cast<const float4*>(&H[(size_t)c3 * 128 + lane * 4]);
        float4 v4 = *reinterpret_cast<const float4*>(&H[(size_t)c4 * 128 + lane * 4]);
        float4 v5 = *reinterpret_cast<const float4*>(&H[(size_t)c5 * 128 + lane * 4]);
        float4 v6 = *reinterpret_cast<const float4*>(&H[(size_t)c6 * 128 + lane * 4]);
        float4 v7 = *reinterpret_cast<const float4*>(&H[(size_t)c7 * 128 + lane * 4]);
        acc.x += w0e * v0.x + w1e * v1.x + w2e * v2.x + w3e * v3.x
               + w4e * v4.x + w5e * v5.x + w6e * v6.x + w7e * v7.x;
        acc.y += w0e * v0.y + w1e * v1.y + w2e * v2.y + w3e * v3.y
               + w4e * v4.y + w5e * v5.y + w6e * v6.y + w7e * v7.y;
        acc.z += w0e * v0.z + w1e * v1.z + w2e * v2.z + w3e * v3.z
               + w4e * v4.z + w5e * v5.z + w6e * v6.z + w7e * v7.z;
        acc.w += w0e * v0.w + w1e * v1.w + w2e * v2.w + w3e * v3.w
               + w4e * v4.w + w5e * v5.w + w6e * v6.w + w7e * v7.w;
    }
    for (; k < e; k++) {
        int cc = __ldg(&g_col[k]);
        float we = __ldg(&g_wv[k]);
        float4 v = *reinterpret_cast<const float4*>(&H[(size_t)cc * 128 + lane * 4]);
        acc.x += we * v.x; acc.y += we * v.y; acc.z += we * v.z; acc.w += we * v.w;
    }

    int c = lane * 4;
    float4 a4 = *reinterpret_cast<const float4*>(&g_bnA[c]);
    float4 b4 = *reinterpret_cast<const float4*>(&g_bnB[c]);
    float4 y;
    y.x = acc.x * a4.x + b4.x;  y.y = acc.y * a4.y + b4.y;
    y.z = acc.z * a4.z + b4.z;  y.w = acc.w * a4.w + b4.w;
    y.x = y.x > 0.f ? y.x : 0.01f * y.x;
    y.y = y.y > 0.f ? y.y : 0.01f * y.y;
    y.z = y.z > 0.f ? y.z : 0.01f * y.z;
    y.w = y.w > 0.f ? y.w : 0.01f * y.w;
    *reinterpret_cast<float4*>(&g_bufA[(size_t)m * 128 + c]) = y;
}

// ---------------- aggregation (layers 1,2): g_agg = agg(H) ----------------
__global__ __launch_bounds__(256) void agg_kernel(const float* __restrict__ H, int n) {
    int wid = threadIdx.x >> 5, lane = threadIdx.x & 31;
    int m = blockIdx.x * 8 + wid;
    if (m >= n) return;

    float dis = g_deg[m];
    float w0 = dis * dis;
    float4 h4 = *reinterpret_cast<const float4*>(&H[(size_t)m * 128 + lane * 4]);
    float4 acc = make_float4(w0 * h4.x, w0 * h4.y, w0 * h4.z, w0 * h4.w);

    int s = g_rowstart[m], e = g_rowstart[m + 1];
    int k = s;
    for (; k + 8 <= e; k += 8) {
        int   c0 = __ldg(&g_col[k]),     c1 = __ldg(&g_col[k + 1]);
        int   c2 = __ldg(&g_col[k + 2]), c3 = __ldg(&g_col[k + 3]);
        int   c4 = __ldg(&g_col[k + 4]), c5 = __ldg(&g_col[k + 5]);
        int   c6 = __ldg(&g_col[k + 6]), c7 = __ldg(&g_col[k + 7]);
        float w0e = __ldg(&g_wv[k]),     w1e = __ldg(&g_wv[k + 1]);
        float w2e = __ldg(&g_wv[k + 2]), w3e = __ldg(&g_wv[k + 3]);
        float w4e = __ldg(&g_wv[k + 4]), w5e = __ldg(&g_wv[k + 5]);
        float w6e = __ldg(&g_wv[k + 6]), w7e = __ldg(&g_wv[k + 7]);
        float4 v0 = *reinterpret_cast<const float4*>(&H[(size_t)c0 * 128 + lane * 4]);
        float4 v1 = *reinterpret_cast<const float4*>(&H[(size_t)c1 * 128 + lane * 4]);
        float4 v2 = *reinterpret_cast<const float4*>(&H[(size_t)c2 * 128 + lane * 4]);
        float4 v3 = *reinterpret_cast<const float4*>(&H[(size_t)c3 * 128 + lane * 4]);
        float4 v4 = *reinterpret_cast<const float4*>(&H[(size_t)c4 * 128 + lane * 4]);
        float4 v5 = *reinterpret_cast<const float4*>(&H[(size_t)c5 * 128 + lane * 4]);
        float4 v6 = *reinterpret_cast<const float4*>(&H[(size_t)c6 * 128 + lane * 4]);
        float4 v7 = *reinterpret_cast<const float4*>(&H[(size_t)c7 * 128 + lane * 4]);
        acc.x += w0e * v0.x + w1e * v1.x + w2e * v2.x + w3e * v3.x
               + w4e * v4.x + w5e * v5.x + w6e * v6.x + w7e * v7.x;
        acc.y += w0e * v0.y + w1e * v1.y + w2e * v2.y + w3e * v3.y
               + w4e * v4.y + w5e * v5.y + w6e * v6.y + w7e * v7.y;
        acc.z += w0e * v0.z + w1e * v1.z + w2e * v2.z + w3e * v3.z
               + w4e * v4.z + w5e * v5.z + w6e * v6.z + w7e * v7.z;
        acc.w += w0e * v0.w + w1e * v1.w + w2e * v2.w + w3e * v3.w
               + w4e * v4.w + w5e * v5.w + w6e * v6.w + w7e * v7.w;
    }
    for (; k < e; k++) {
        int cc = __ldg(&g_col[k]);
        float we = __ldg(&g_wv[k]);
        float4 v = *reinterpret_cast<const float4*>(&H[(size_t)cc * 128 + lane * 4]);
        acc.x += we * v.x; acc.y += we * v.y; acc.z += we * v.z; acc.w += we * v.w;
    }
    *reinterpret_cast<float4*>(&g_agg[(size_t)m * 128 + lane * 4]) = acc;
}

// ---------------- GEMM + BN + residual + lrelu (layer 1) ----------------
template <int HASRES>
__global__ __launch_bounds__(256) void gemm_bn_kernel(const float* __restrict__ WT,
                                                      int layer, const float* __restrict__ H,
                                                      float* __restrict__ out, int M) {
    extern __shared__ float sm[];
    float* As = sm;
    float* Ws = sm + 128 * APITCH;

    int tid = threadIdx.x;
    int wid = tid >> 5, lane = tid & 31;
    int m0 = blockIdx.x * 128;

    #pragma unroll
    for (int it = 0; it < 16; it++) {
        int idx = tid + it * 256;
        int r = idx >> 5, q = idx & 31;
        int m = m0 + r;
        float4 v = make_float4(0.f, 0.f, 0.f, 0.f);
        if (m < M) v = *reinterpret_cast<const float4*>(&g_agg[(size_t)m * 128 + q * 4]);
        float* p = &As[r * APITCH + q * 4];
        p[0] = to_tf32(v.x); p[1] = to_tf32(v.y); p[2] = to_tf32(v.z); p[3] = to_tf32(v.w);
    }
    #pragma unroll
    for (int it = 0; it < 16; it++) {
        int idx = tid + it * 256;
        int r = idx >> 5, q = idx & 31;
        float4 v = *reinterpret_cast<const float4*>(&WT[(size_t)r * 128 + q * 4]);
        *reinterpret_cast<float4*>(&Ws[r * APITCH + q * 4]) = v;
    }
    __syncthreads();

    int wm = wid & 3, wn = wid >> 2;
    int grp = lane >> 2, tg = lane & 3;
    int arow = wm * 32 + grp;
    int brow = wn * 64 + grp;

    float d[2][8][4];
    #pragma unroll
    for (int i = 0; i < 2; i++)
        #pragma unroll
        for (int j = 0; j < 8; j++)
            #pragma unroll
            for (int q = 0; q < 4; q++) d[i][j][q] = 0.0f;

    #pragma unroll
    for (int k0 = 0; k0 < 16; k0++) {
        int kk = k0 * 8 + tg;
        uint32_t a[2][4];
        #pragma unroll
        for (int mf = 0; mf < 2; mf++) {
            const float* ap = &As[(arow + mf * 16) * APITCH + kk];
            a[mf][0] = __float_as_uint(ap[0]);
            a[mf][2] = __float_as_uint(ap[4]);
            a[mf][1] = __float_as_uint(ap[8 * APITCH]);
            a[mf][3] = __float_as_uint(ap[8 * APITCH + 4]);
        }
        uint32_t b[8][2];
        #pragma unroll
        for (int nf = 0; nf < 8; nf++) {
            const float* bp = &Ws[(brow + nf * 8) * APITCH + kk];
            b[nf][0] = __float_as_uint(bp[0]);
            b[nf][1] = __float_as_uint(bp[4]);
        }
        #pragma unroll
        for (int mf = 0; mf < 2; mf++)
            #pragma unroll
            for (int nf = 0; nf < 8; nf++)
                mma8(d[mf][nf], a[mf], b[nf]);
    }

    const float* bnA = &g_bnA[layer * C];
    const float* bnB = &g_bnB[layer * C];
    #pragma unroll
    for (int mf = 0; mf < 2; mf++) {
        #pragma unroll
        for (int half = 0; half < 2; half++) {
            int m = m0 + wm * 32 + mf * 16 + half * 8 + grp;
            if (m < M) {
                #pragma unroll
                for (int nf = 0; nf < 8; nf++) {
                    int ncol = wn * 64 + nf * 8 + tg * 2;
                    float2 v;
                    v.x = d[mf][nf][half * 2 + 0] * bnA[ncol]     + bnB[ncol];
                    v.y = d[mf][nf][half * 2 + 1] * bnA[ncol + 1] + bnB[ncol + 1];
                    if (HASRES) {
                        float2 rv = *reinterpret_cast<const float2*>(&H[(size_t)m * 128 + ncol]);
                        v.x += rv.x; v.y += rv.y;
                    }
                    v.x = v.x > 0.f ? v.x : 0.01f * v.x;
                    v.y = v.y > 0.f ? v.y : 0.01f * v.y;
                    *reinterpret_cast<float2*>(&out[(size_t)m * 128 + ncol]) = v;
                }
            }
        }
    }
}

// ---------------- fused tail: layer-2 GEMM+BN+res+lrelu -> lin1+lrelu -> lin2 -> out ----------------
__global__ __launch_bounds__(256) void tail_kernel(const float* __restrict__ H,
                                                   const float* __restrict__ WcT,
                                                   const float* __restrict__ WT1,
                                                   const float* __restrict__ bias1,
                                                   const float* __restrict__ WT2,
                                                   const float* __restrict__ bias2,
                                                   float* __restrict__ out, int M) {
    extern __shared__ float sm[];
    float* As = sm;
    float* Ws = sm + 128 * APITCH;

    int tid = threadIdx.x;
    int wid = tid >> 5, lane = tid & 31;
    int m0 = blockIdx.x * 128;

    {
        int z = blockIdx.x * 256 + tid;
        if (z < NN) { g_deg[z] = 0.0f; g_cnt[z] = 0; }
        if (z < NSCB) g_bflag[z] = 0;
    }

    int wm = wid & 3, wn = wid >> 2;
    int grp = lane >> 2, tg = lane & 3;
    int arow = wm * 32 + grp;

    #pragma unroll
    for (int it = 0; it < 16; it++) {
        int idx = tid + it * 256;
        int r = idx >> 5, q = idx & 31;
        int m = m0 + r;
        float4 v = make_float4(0.f, 0.f, 0.f, 0.f);
        if (m < M) v = *reinterpret_cast<const float4*>(&g_agg[(size_t)m * 128 + q * 4]);
        float* p = &As[r * APITCH + q * 4];
        p[0] = to_tf32(v.x); p[1] = to_tf32(v.y); p[2] = to_tf32(v.z); p[3] = to_tf32(v.w);
    }
    #pragma unroll
    for (int it = 0; it < 16; it++) {
        int idx = tid + it * 256;
        int r = idx >> 5, q = idx & 31;
        float4 v = *reinterpret_cast<const float4*>(&WcT[(size_t)r * 128 + q * 4]);
        *reinterpret_cast<float4*>(&Ws[r * APITCH + q * 4]) = v;
    }
    __syncthreads();

    float d[2][8][4];

    // ---- stage 0: layer-2 GEMM ----
    {
        int brow = wn * 64 + grp;
        #pragma unroll
        for (int i = 0; i < 2; i++)
            #pragma unroll
            for (int j = 0; j < 8; j++)
                #pragma unroll
                for (int q = 0; q < 4; q++) d[i][j][q] = 0.0f;
        #pragma unroll
        for (int k0 = 0; k0 < 16; k0++) {
            int kk = k0 * 8 + tg;
            uint32_t a[2][4];
            #pragma unroll
            for (int mf = 0; mf < 2; mf++) {
                const float* ap = &As[(arow + mf * 16) * APITCH + kk];
                a[mf][0] = __float_as_uint(ap[0]);
                a[mf][2] = __float_as_uint(ap[4]);
                a[mf][1] = __float_as_uint(ap[8 * APITCH]);
                a[mf][3] = __float_as_uint(ap[8 * APITCH + 4]);
            }
            uint32_t b[8][2];
            #pragma unroll
            for (int nf = 0; nf < 8; nf++) {
                const float* bp = &Ws[(brow + nf * 8) * APITCH + kk];
                b[nf][0] = __float_as_uint(bp[0]);
                b[nf][1] = __float_as_uint(bp[4]);
            }
            #pragma unroll
            for (int mf = 0; mf < 2; mf++)
                #pragma unroll
                for (int nf = 0; nf < 8; nf++)
                    mma8(d[mf][nf], a[mf], b[nf]);
        }
    }
    __syncthreads();

    // z0 = lrelu(bn2(d) + residual) -> As ; stage Ws = lin1
    {
        const float* bnA = &g_bnA[2 * C];
        const float* bnB = &g_bnB[2 * C];
        #pragma unroll
        for (int mf = 0; mf < 2; mf++) {
            #pragma unroll
            for (int half = 0; half < 2; half++) {
                int r = wm * 32 + mf * 16 + half * 8 + grp;
                int m = m0 + r;
                #pragma unroll
                for (int nf = 0; nf < 8; nf++) {
                    int ncol = wn * 64 + nf * 8 + tg * 2;
                    float vx = d[mf][nf][half * 2 + 0] * bnA[ncol]     + bnB[ncol];
                    float vy = d[mf][nf][half * 2 + 1] * bnA[ncol + 1] + bnB[ncol + 1];
                    if (m < M) {
                        float2 rv = *reinterpret_cast<const float2*>(&H[(size_t)m * 128 + ncol]);
                        vx += rv.x; vy += rv.y;
                    }
                    vx = vx > 0.f ? vx : 0.01f * vx;
                    vy = vy > 0.f ? vy : 0.01f * vy;
                    As[r * APITCH + ncol]     = to_tf32(vx);
                    As[r * APITCH + ncol + 1] = to_tf32(vy);
                }
            }
        }
        #pragma unroll
        for (int it = 0; it < 16; it++) {
            int idx = tid + it * 256;
            int r = idx >> 5, q = idx & 31;
            float4 v = *reinterpret_cast<const float4*>(&WT1[(size_t)r * 128 + q * 4]);
            *reinterpret_cast<float4*>(&Ws[r * APITCH + q * 4]) = v;
        }
    }
    __syncthreads();

    // ---- stage 1: lin1 ----
    {
        int brow = wn * 64 + grp;
        #pragma unroll
        for (int i = 0; i < 2; i++)
            #pragma unroll
            for (int j = 0; j < 8; j++)
                #pragma unroll
                for (int q = 0; q < 4; q++) d[i][j][q] = 0.0f;
        #pragma unroll
        for (int k0 = 0; k0 < 16; k0++) {
            int kk = k0 * 8 + tg;
            uint32_t a[2][4];
            #pragma unroll
            for (int mf = 0; mf < 2; mf++) {
                const float* ap = &As[(arow + mf * 16) * APITCH + kk];
                a[mf][0] = __float_as_uint(ap[0]);
                a[mf][2] = __float_as_uint(ap[4]);
                a[mf][1] = __float_as_uint(ap[8 * APITCH]);
                a[mf][3] = __float_as_uint(ap[8 * APITCH + 4]);
            }
            uint32_t b[8][2];
            #pragma unroll
            for (int nf = 0; nf < 8; nf++) {
                const float* bp = &Ws[(brow + nf * 8) * APITCH + kk];
                b[nf][0] = __float_as_uint(bp[0]);
                b[nf][1] = __float_as_uint(bp[4]);
            }
            #pragma unroll
            for (int mf = 0; mf < 2; mf++)
                #pragma unroll
                for (int nf = 0; nf < 8; nf++)
                    mma8(d[mf][nf], a[mf], b[nf]);
        }
    }
    __syncthreads();

    // z1 = lrelu(d + bias1) -> As ; stage Ws = lin2
    {
        #pragma unroll
        for (int mf = 0; mf < 2; mf++) {
            #pragma unroll
            for (int half = 0; half < 2; half++) {
                int r = wm * 32 + mf * 16 + half * 8 + grp;
                #pragma unroll
                for (int nf = 0; nf < 8; nf++) {
                    int ncol = wn * 64 + nf * 8 + tg * 2;
                    float vx = d[mf][nf][half * 2 + 0] + bias1[ncol];
                    float vy = d[mf][nf][half * 2 + 1] + bias1[ncol + 1];
                    vx = vx > 0.f ? vx : 0.01f * vx;
                    vy = vy > 0.f ? vy : 0.01f * vy;
                    As[r * APITCH + ncol]     = to_tf32(vx);
                    As[r * APITCH + ncol + 1] = to_tf32(vy);
                }
            }
        }
        #pragma unroll
        for (int it = 0; it < 8; it++) {
            int idx = tid + it * 256;
            int r = idx >> 5, q = idx & 31;
            float4 v = *reinterpret_cast<const float4*>(&WT2[(size_t)r * 128 + q * 4]);
            *reinterpret_cast<float4*>(&Ws[r * APITCH + q * 4]) = v;
        }
    }
    __syncthreads();

    // ---- stage 2: lin2 -> gmem ----
    {
        int brow = wn * 32 + grp;
        float d2[2][4][4];
        #pragma unroll
        for (int i = 0; i < 2; i++)
            #pragma unroll
            for (int j = 0; j < 4; j++)
                #pragma unroll
                for (int q = 0; q < 4; q++) d2[i][j][q] = 0.0f;
        #pragma unroll
        for (int k0 = 0; k0 < 16; k0++) {
            int kk = k0 * 8 + tg;
            uint32_t a[2][4];
            #pragma unroll
            for (int mf = 0; mf < 2; mf++) {
                const float* ap = &As[(arow + mf * 16) * APITCH + kk];
                a[mf][0] = __float_as_uint(ap[0]);
                a[mf][2] = __float_as_uint(ap[4]);
                a[mf][1] = __float_as_uint(ap[8 * APITCH]);
                a[mf][3] = __float_as_uint(ap[8 * APITCH + 4]);
            }
            uint32_t b[4][2];
            #pragma unroll
            for (int nf = 0; nf < 4; nf++) {
                const float* bp = &Ws[(brow + nf * 8) * APITCH + kk];
                b[nf][0] = __float_as_uint(bp[0]);
                b[nf][1] = __float_as_uint(bp[4]);
            }
            #pragma unroll
            for (int mf = 0; mf < 2; mf++)
                #pragma unroll
                for (int nf = 0; nf < 4; nf++)
                    mma8(d2[mf][nf], a[mf], b[nf]);
        }

        #pragma unroll
        for (int mf = 0; mf < 2; mf++) {
            #pragma unroll
            for (int half = 0; half < 2; half++) {
                int m = m0 + wm * 32 + mf * 16 + half * 8 + grp;
                if (m < M) {
                    #pragma unroll
                    for (int nf = 0; nf < 4; nf++) {
                        int ncol = wn * 32 + nf * 8 + tg * 2;
                        float2 v;
                        v.x = d2[mf][nf][half * 2 + 0] + bias2[ncol];
                        v.y = d2[mf][nf][half * 2 + 1] + bias2[ncol + 1];
                        *reinterpret_cast<float2*>(&out[(size_t)m * COUT + ncol]) = v;
                    }
                }
            }
        }
    }
}

// ---------------- launch ----------------
extern "C" void kernel_launch(void* const* d_in, const int* in_sizes, int n_in,
                              void* d_out, int out_size) {
    const float* x       = (const float*)d_in[0];
    const int*   ei      = (const int*)d_in[1];
    const float* ew      = (const float*)d_in[2];
    const float* w1      = (const float*)d_in[3];
    const float* b1      = (const float*)d_in[4];
    const float* bn1_g   = (const float*)d_in[5];
    const float* bn1_b   = (const float*)d_in[6];
    const float* bn1_m   = (const float*)d_in[7];
    const float* bn1_v   = (const float*)d_in[8];
    const float* conv_ws = (const float*)d_in[9];
    const float* conv_bs = (const float*)d_in[10];
    const float* bns_g   = (const float*)d_in[11];
    const float* bns_b   = (const float*)d_in[12];
    const float* bns_m   = (const float*)d_in[13];
    const float* bns_v   = (const float*)d_in[14];
    const float* lin1_w  = (const float*)d_in[15];
    const float* lin1_b  = (const float*)d_in[16];
    const float* lin2_w  = (const float*)d_in[17];
    const float* lin2_b  = (const float*)d_in[18];

    int n = in_sizes[0] / C;     // 50000
    int e = in_sizes[2];         // 800000
    const int* srcp = ei;
    const int* dstp = ei + e;

    const int SMEM_GEMM = 256 * APITCH * 4;   // 135168

    cudaFuncSetAttribute(gemm_plain_kernel, cudaFuncAttributeMaxDynamicSharedMemorySize, SMEM_GEMM);
    cudaFuncSetAttribute(gemm_bn_kernel<1>, cudaFuncAttributeMaxDynamicSharedMemorySize, SMEM_GEMM);
    cudaFuncSetAttribute(tail_kernel,       cudaFuncAttributeMaxDynamicSharedMemorySize, SMEM_GEMM);

    float* wt = nullptr;   cudaGetSymbolAddress((void**)&wt, g_wt);
    float* bufA = nullptr; cudaGetSymbolAddress((void**)&bufA, g_bufA);
    float* bufB = nullptr; cudaGetSymbolAddress((void**)&bufB, g_bufB);

    // side stream + fork/join events (created on first call = uncaptured run)
    static cudaStream_t sB = nullptr;
    static cudaEvent_t evFork = nullptr, evScan = nullptr, evJoin = nullptr;
    if (!sB) {
        cudaStreamCreateWithFlags(&sB, cudaStreamNonBlocking);
        cudaEventCreateWithFlags(&evFork, cudaEventDisableTiming);
        cudaEventCreateWithFlags(&evScan, cudaEventDisableTiming);
        cudaEventCreateWithFlags(&evJoin, cudaEventDisableTiming);
    }

    int nb_e = (e + 255) / 256;
    int ablocks = (n + 7) / 8;
    int gblocks = (n + 127) / 128;
    int eh = (e / 2 + 255) & ~255;            // half split, aligned

    // fork
    cudaEventRecord(evFork, 0);
    cudaStreamWaitEvent(sB, evFork, 0);

    // stream A: count (+rank) -> scan -> fill first half
    count_kernel<<<nb_e, 256>>>(dstp, ew, e);
    scan_kernel<<<NSCB, SCAN_B>>>(n, b1, bn1_g, bn1_b, bn1_m, bn1_v,
                                  conv_bs, bns_g, bns_b, bns_m, bns_v);
    cudaEventRecord(evScan, 0);
    fill_kernel<<<(eh + 255) / 256, 256>>>(srcp, dstp, ew, 0, eh);

    // stream B: weight transpose -> layer-0 GEMM -> fill second half (after scan)
    tr_kernel<<<(5 * 16384 - 8192 + 255) / 256, 256, 0, sB>>>(w1, conv_ws, lin1_w, lin2_w);
    gemm_plain_kernel<<<gblocks, 256, SMEM_GEMM, sB>>>(x, wt + 0 * 16384, n);
    cudaStreamWaitEvent(sB, evScan, 0);
    fill_kernel<<<(e - eh + 255) / 256, 256, 0, sB>>>(srcp, dstp, ew, eh, e);

    // join
    cudaEventRecord(evJoin, sB);
    cudaStreamWaitEvent(0, evJoin, 0);

    // layer 0: bufA = lrelu(bn0(agg(tmp)))
    agg_bn_kernel<<<ablocks, 256>>>(n);

    // layer 1
    agg_kernel<<<ablocks, 256>>>(bufA, n);
    gemm_bn_kernel<1><<<gblocks, 256, SMEM_GEMM>>>(wt + 1 * 16384, 1, bufA, bufB, n);

    // layer 2 + heads fused (also restores zero invariants)
    agg_kernel<<<ablocks, 256>>>(bufB, n);
    tail_kernel<<<gblocks, 256, SMEM_GEMM>>>(bufB, wt + 2 * 16384, wt + 3 * 16384, lin1_b,
                                             wt + 4 * 16384, lin2_b, (float*)d_out, n);
}

// round 14
// speedup vs baseline: 1.4934x; 1.0016x over previous
#include <cuda_runtime.h>
#include <cuda_bf16.h>
#include <cstdint>

// Problem constants (fixed by the dataset)
#define NN   50000
#define EE   800000
#define C    128
#define COUT 64
#define EPSV 1e-5f
#define APITCH 132
#define SCAN_B 1024
#define NSCB   ((NN + SCAN_B - 1) / SCAN_B)   // 49

// ---------------- device scratch (no allocations allowed) ----------------
// Invariant: g_cnt, g_deg, g_bflag are ZERO at the start of every call.
// (zero at module load; tail_kernel re-zeroes all three at the end of each call.)
__device__ float g_deg[NN];
__device__ int   g_cnt[NN];
__device__ int   g_rowstart[NN + 1];
__device__ int   g_rank[EE];           // per-edge rank within its dst row
__device__ int   g_btot[NSCB];
__device__ int   g_bflag[NSCB];
__device__ int2  g_cw[EE];             // interleaved (col, wv-bits)
__device__ float g_agg[(size_t)NN * C];
__device__ float g_bufA[(size_t)NN * C];
__device__ float g_bufB[(size_t)NN * C];
__device__ float g_bnA[3 * C];
__device__ float g_bnB[3 * C];
__device__ float g_wt[5 * 128 * 128];  // transposed weights WT[n][k], tf32-rounded

__device__ __forceinline__ float to_tf32(float f) {
    uint32_t u;
    asm("cvt.rna.tf32.f32 %0, %1;" : "=r"(u) : "f"(f));
    return __uint_as_float(u);
}

__device__ __forceinline__ void mma8(float* d, const uint32_t* a, const uint32_t* b) {
    asm volatile(
        "mma.sync.aligned.m16n8k8.row.col.f32.tf32.tf32.f32 "
        "{%0,%1,%2,%3}, {%4,%5,%6,%7}, {%8,%9}, {%0,%1,%2,%3};"
        : "+f"(d[0]), "+f"(d[1]), "+f"(d[2]), "+f"(d[3])
        : "r"(a[0]), "r"(a[1]), "r"(a[2]), "r"(a[3]), "r"(b[0]), "r"(b[1]));
}

// ---------------- aggregation core: smem-staged (col,w) pairs ----------------
// Per 32 edges: ONE coalesced LDG.64 (lanes 0-31) -> smem -> LDS.64 broadcasts.
// Cuts LDG-pipe instructions ~3x vs scalar col/wv loads.
__device__ __forceinline__ float4 agg_row(const float* __restrict__ H, int2 (*stage)[32],
                                          int wid, int lane, int m) {
    float dis = g_deg[m];
    float w0 = dis * dis;
    float4 h4 = *reinterpret_cast<const float4*>(&H[(size_t)m * 128 + lane * 4]);
    float4 acc = make_float4(w0 * h4.x, w0 * h4.y, w0 * h4.z, w0 * h4.w);

    int s = g_rowstart[m], e = g_rowstart[m + 1];
    for (int kb = s; kb < e; kb += 32) {
        int nn = e - kb; if (nn > 32) nn = 32;
        if (lane < nn) stage[wid][lane] = __ldg(&g_cw[kb + lane]);
        __syncwarp();
        int kk = 0;
        for (; kk + 8 <= nn; kk += 8) {
            int2 q0 = stage[wid][kk + 0], q1 = stage[wid][kk + 1];
            int2 q2 = stage[wid][kk + 2], q3 = stage[wid][kk + 3];
            int2 q4 = stage[wid][kk + 4], q5 = stage[wid][kk + 5];
            int2 q6 = stage[wid][kk + 6], q7 = stage[wid][kk + 7];
            float4 v0 = *reinterpret_cast<const float4*>(&H[(size_t)q0.x * 128 + lane * 4]);
            float4 v1 = *reinterpret_cast<const float4*>(&H[(size_t)q1.x * 128 + lane * 4]);
            float4 v2 = *reinterpret_cast<const float4*>(&H[(size_t)q2.x * 128 + lane * 4]);
            float4 v3 = *reinterpret_cast<const float4*>(&H[(size_t)q3.x * 128 + lane * 4]);
            float4 v4 = *reinterpret_cast<const float4*>(&H[(size_t)q4.x * 128 + lane * 4]);
            float4 v5 = *reinterpret_cast<const float4*>(&H[(size_t)q5.x * 128 + lane * 4]);
            float4 v6 = *reinterpret_cast<const float4*>(&H[(size_t)q6.x * 128 + lane * 4]);
            float4 v7 = *reinterpret_cast<const float4*>(&H[(size_t)q7.x * 128 + lane * 4]);
            float w0e = __int_as_float(q0.y), w1e = __int_as_float(q1.y);
            float w2e = __int_as_float(q2.y), w3e = __int_as_float(q3.y);
            float w4e = __int_as_float(q4.y), w5e = __int_as_float(q5.y);
            float w6e = __int_as_float(q6.y), w7e = __int_as_float(q7.y);
            acc.x += w0e * v0.x + w1e * v1.x + w2e * v2.x + w3e * v3.x
                   + w4e * v4.x + w5e * v5.x + w6e * v6.x + w7e * v7.x;
            acc.y += w0e * v0.y + w1e * v1.y + w2e * v2.y + w3e * v3.y
                   + w4e * v4.y + w5e * v5.y + w6e * v6.y + w7e * v7.y;
            acc.z += w0e * v0.z + w1e * v1.z + w2e * v2.z + w3e * v3.z
                   + w4e * v4.z + w5e * v5.z + w6e * v6.z + w7e * v7.z;
            acc.w += w0e * v0.w + w1e * v1.w + w2e * v2.w + w3e * v3.w
                   + w4e * v4.w + w5e * v5.w + w6e * v6.w + w7e * v7.w;
        }
        for (; kk < nn; kk++) {
            int2 q = stage[wid][kk];
            float we = __int_as_float(q.y);
            float4 v = *reinterpret_cast<const float4*>(&H[(size_t)q.x * 128 + lane * 4]);
            acc.x += we * v.x; acc.y += we * v.y; acc.z += we * v.z; acc.w += we * v.w;
        }
        __syncwarp();
    }
    return acc;
}

// ---------------- stream A kernel 0: edge count/degree atomics + rank recording ----------------
__global__ void count_kernel(const int* __restrict__ dst, const float* __restrict__ ew, int e) {
    int i = blockIdx.x * blockDim.x + threadIdx.x;
    if (i < e) {
        int d = dst[i];
        g_rank[i] = atomicAdd(&g_cnt[d], 1);
        atomicAdd(&g_deg[d], ew[i]);
    }
}

// ---------------- stream B kernel 0: weight transpose (tf32-rounded) ----------------
__global__ void tr_kernel(const float* __restrict__ w1, const float* __restrict__ conv_ws,
                          const float* __restrict__ lin1_w, const float* __restrict__ lin2_w) {
    int g = blockIdx.x * 256 + threadIdx.x;
    if (g < 4 * 16384) {
        int mat = g >> 14, idx = g & 16383;
        int k = idx >> 7, nn = idx & 127;
        const float* W = (mat == 0) ? w1 : ((mat == 3) ? lin1_w : (conv_ws + (mat - 1) * 16384));
        g_wt[mat * 16384 + nn * 128 + k] = to_tf32(W[k * 128 + nn]);
    } else if (g < 4 * 16384 + 8192) {
        int idx = g - 4 * 16384;
        int k = idx >> 6, nn = idx & 63;
        g_wt[4 * 16384 + nn * 128 + k] = to_tf32(lin2_w[k * 64 + nn]);
    }
}

// ---------------- single-pass scan (decoupled lookback) + dis + BN fold ----------------
__global__ __launch_bounds__(SCAN_B) void scan_kernel(int n, const float* b1,
                                  const float* g1, const float* be1, const float* m1, const float* v1,
                                  const float* conv_bs,
                                  const float* gs, const float* bes, const float* ms, const float* vs) {
    __shared__ int wsum[32];
    __shared__ int s_prefix;
    int t = threadIdx.x, lane = t & 31, w = t >> 5;
    int b = blockIdx.x;
    int i = b * SCAN_B + t;

    int v = (i < n) ? g_cnt[i] : 0;
    int x = v;
    #pragma unroll
    for (int o = 1; o < 32; o <<= 1) { int y = __shfl_up_sync(0xffffffffu, x, o); if (lane >= o) x += y; }
    if (lane == 31) wsum[w] = x;
    __syncthreads();
    if (w == 0) {
        int s = wsum[lane];
        #pragma unroll
        for (int o = 1; o < 32; o <<= 1) { int y = __shfl_up_sync(0xffffffffu, s, o); if (lane >= o) s += y; }
        wsum[lane] = s;
    }
    __syncthreads();
    int incl = x + (w > 0 ? wsum[w - 1] : 0);
    int btotal = wsum[31];

    if (t == 0) {
        atomicExch(&g_btot[b], btotal);
        __threadfence();
        atomicExch(&g_bflag[b], 1);
    }
    if (w == 1) {
        int sum = 0;
        for (int j = lane; j < b; j += 32) {
            while (atomicAdd(&g_bflag[j], 0) == 0) {}
            sum += atomicAdd(&g_btot[j], 0);
        }
        #pragma unroll
        for (int o = 16; o > 0; o >>= 1) sum += __shfl_down_sync(0xffffffffu, sum, o);
        if (lane == 0) s_prefix = sum;
    }
    __syncthreads();
    int prefix = s_prefix;

    if (i < n) {
        g_rowstart[i] = prefix + incl - v;
        g_deg[i] = rsqrtf(g_deg[i] + 1.0f);   // + self loop
    }
    if (b == NSCB - 1 && t == 0) g_rowstart[n] = prefix + btotal;

    if (b == 0 && t < C) {
        int c = t;
        float sc = g1[c] * rsqrtf(v1[c] + EPSV);
        g_bnA[c] = sc;
        g_bnB[c] = be1[c] + (b1[c] - m1[c]) * sc;
        #pragma unroll
        for (int l = 0; l < 2; l++) {
            float s2 = gs[l * C + c] * rsqrtf(vs[l * C + c] + EPSV);
            g_bnA[(1 + l) * C + c] = s2;
            g_bnB[(1 + l) * C + c] = bes[l * C + c] + (conv_bs[l * C + c] - ms[l * C + c]) * s2;
        }
    }
}

// ---------------- CSR fill: atomic-free, single 8B scatter store ----------------
__global__ void fill_kernel(const int* __restrict__ src, const int* __restrict__ dst,
                            const float* __restrict__ ew, int lo, int hi) {
    int i = lo + blockIdx.x * blockDim.x + threadIdx.x;
    if (i < hi) {
        int s = src[i], d = dst[i];
        int pos = g_rowstart[d] + g_rank[i];
        float w = g_deg[s] * ew[i] * g_deg[d];
        g_cw[pos] = make_int2(s, __float_as_int(w));
    }
}

// ---------------- plain GEMM (no epilogue): g_agg = tf32(X) @ W ----------------
__global__ __launch_bounds__(256) void gemm_plain_kernel(const float* __restrict__ X,
                                                         const float* __restrict__ WT, int M) {
    extern __shared__ float sm[];
    float* As = sm;
    float* Ws = sm + 128 * APITCH;

    int tid = threadIdx.x;
    int wid = tid >> 5, lane = tid & 31;
    int m0 = blockIdx.x * 128;

    #pragma unroll
    for (int it = 0; it < 16; it++) {
        int idx = tid + it * 256;
        int r = idx >> 5, q = idx & 31;
        int m = m0 + r;
        float4 v = make_float4(0.f, 0.f, 0.f, 0.f);
        if (m < M) v = *reinterpret_cast<const float4*>(&X[(size_t)m * 128 + q * 4]);
        float* p = &As[r * APITCH + q * 4];
        p[0] = to_tf32(v.x); p[1] = to_tf32(v.y); p[2] = to_tf32(v.z); p[3] = to_tf32(v.w);
    }
    #pragma unroll
    for (int it = 0; it < 16; it++) {
        int idx = tid + it * 256;
        int r = idx >> 5, q = idx & 31;
        float4 v = *reinterpret_cast<const float4*>(&WT[(size_t)r * 128 + q * 4]);
        *reinterpret_cast<float4*>(&Ws[r * APITCH + q * 4]) = v;
    }
    __syncthreads();

    int wm = wid & 3, wn = wid >> 2;
    int grp = lane >> 2, tg = lane & 3;
    int arow = wm * 32 + grp;
    int brow = wn * 64 + grp;

    float d[2][8][4];
    #pragma unroll
    for (int i = 0; i < 2; i++)
        #pragma unroll
        for (int j = 0; j < 8; j++)
            #pragma unroll
            for (int q = 0; q < 4; q++) d[i][j][q] = 0.0f;

    #pragma unroll
    for (int k0 = 0; k0 < 16; k0++) {
        int kk = k0 * 8 + tg;
        uint32_t a[2][4];
        #pragma unroll
        for (int mf = 0; mf < 2; mf++) {
            const float* ap = &As[(arow + mf * 16) * APITCH + kk];
            a[mf][0] = __float_as_uint(ap[0]);
            a[mf][2] = __float_as_uint(ap[4]);
            a[mf][1] = __float_as_uint(ap[8 * APITCH]);
            a[mf][3] = __float_as_uint(ap[8 * APITCH + 4]);
        }
        uint32_t b[8][2];
        #pragma unroll
        for (int nf = 0; nf < 8; nf++) {
            const float* bp = &Ws[(brow + nf * 8) * APITCH + kk];
            b[nf][0] = __float_as_uint(bp[0]);
            b[nf][1] = __float_as_uint(bp[4]);
        }
        #pragma unroll
        for (int mf = 0; mf < 2; mf++)
            #pragma unroll
            for (int nf = 0; nf < 8; nf++)
                mma8(d[mf][nf], a[mf], b[nf]);
    }

    #pragma unroll
    for (int mf = 0; mf < 2; mf++) {
        #pragma unroll
        for (int half = 0; half < 2; half++) {
            int m = m0 + wm * 32 + mf * 16 + half * 8 + grp;
            if (m < M) {
                #pragma unroll
                for (int nf = 0; nf < 8; nf++) {
                    int ncol = wn * 64 + nf * 8 + tg * 2;
                    float2 v = make_float2(d[mf][nf][half * 2 + 0], d[mf][nf][half * 2 + 1]);
                    *reinterpret_cast<float2*>(&g_agg[(size_t)m * 128 + ncol]) = v;
                }
            }
        }
    }
}

// ---------------- layer-0 aggregation + BN + lrelu: bufA = lrelu(bn0(agg(tmp))) ----------------
__global__ __launch_bounds__(256) void agg_bn_kernel(int n) {
    __shared__ int2 stage[8][32];
    int wid = threadIdx.x >> 5, lane = threadIdx.x & 31;
    int m = blockIdx.x * 8 + wid;
    if (m >= n) return;

    float4 acc = agg_row(g_agg, stage, wid, lane, m);

    int c = lane * 4;
    float4 a4 = *reinterpret_cast<const float4*>(&g_bnA[c]);
    float4 b4 = *reinterpret_cast<const float4*>(&g_bnB[c]);
    float4 y;
    y.x = acc.x * a4.x + b4.x;  y.y = acc.y * a4.y + b4.y;
    y.z = acc.z * a4.z + b4.z;  y.w = acc.w * a4.w + b4.w;
    y.x = y.x > 0.f ? y.x : 0.01f * y.x;
    y.y = y.y > 0.f ? y.y : 0.01f * y.y;
    y.z = y.z > 0.f ? y.z : 0.01f * y.z;
    y.w = y.w > 0.f ? y.w : 0.01f * y.w;
    *reinterpret_cast<float4*>(&g_bufA[(size_t)m * 128 + c]) = y;
}

// ---------------- aggregation (layers 1,2): g_agg = agg(H) ----------------
__global__ __launch_bounds__(256) void agg_kernel(const float* __restrict__ H, int n) {
    __shared__ int2 stage[8][32];
    int wid = threadIdx.x >> 5, lane = threadIdx.x & 31;
    int m = blockIdx.x * 8 + wid;
    if (m >= n) return;

    float4 acc = agg_row(H, stage, wid, lane, m);
    *reinterpret_cast<float4*>(&g_agg[(size_t)m * 128 + lane * 4]) = acc;
}

// ---------------- GEMM + BN + residual + lrelu (layer 1) ----------------
template <int HASRES>
__global__ __launch_bounds__(256) void gemm_bn_kernel(const float* __restrict__ WT,
                                                      int layer, const float* __restrict__ H,
                                                      float* __restrict__ out, int M) {
    extern __shared__ float sm[];
    float* As = sm;
    float* Ws = sm + 128 * APITCH;

    int tid = threadIdx.x;
    int wid = tid >> 5, lane = tid & 31;
    int m0 = blockIdx.x * 128;

    #pragma unroll
    for (int it = 0; it < 16; it++) {
        int idx = tid + it * 256;
        int r = idx >> 5, q = idx & 31;
        int m = m0 + r;
        float4 v = make_float4(0.f, 0.f, 0.f, 0.f);
        if (m < M) v = *reinterpret_cast<const float4*>(&g_agg[(size_t)m * 128 + q * 4]);
        float* p = &As[r * APITCH + q * 4];
        p[0] = to_tf32(v.x); p[1] = to_tf32(v.y); p[2] = to_tf32(v.z); p[3] = to_tf32(v.w);
    }
    #pragma unroll
    for (int it = 0; it < 16; it++) {
        int idx = tid + it * 256;
        int r = idx >> 5, q = idx & 31;
        float4 v = *reinterpret_cast<const float4*>(&WT[(size_t)r * 128 + q * 4]);
        *reinterpret_cast<float4*>(&Ws[r * APITCH + q * 4]) = v;
    }
    __syncthreads();

    int wm = wid & 3, wn = wid >> 2;
    int grp = lane >> 2, tg = lane & 3;
    int arow = wm * 32 + grp;
    int brow = wn * 64 + grp;

    float d[2][8][4];
    #pragma unroll
    for (int i = 0; i < 2; i++)
        #pragma unroll
        for (int j = 0; j < 8; j++)
            #pragma unroll
            for (int q = 0; q < 4; q++) d[i][j][q] = 0.0f;

    #pragma unroll
    for (int k0 = 0; k0 < 16; k0++) {
        int kk = k0 * 8 + tg;
        uint32_t a[2][4];
        #pragma unroll
        for (int mf = 0; mf < 2; mf++) {
            const float* ap = &As[(arow + mf * 16) * APITCH + kk];
            a[mf][0] = __float_as_uint(ap[0]);
            a[mf][2] = __float_as_uint(ap[4]);
            a[mf][1] = __float_as_uint(ap[8 * APITCH]);
            a[mf][3] = __float_as_uint(ap[8 * APITCH + 4]);
        }
        uint32_t b[8][2];
        #pragma unroll
        for (int nf = 0; nf < 8; nf++) {
            const float* bp = &Ws[(brow + nf * 8) * APITCH + kk];
            b[nf][0] = __float_as_uint(bp[0]);
            b[nf][1] = __float_as_uint(bp[4]);
        }
        #pragma unroll
        for (int mf = 0; mf < 2; mf++)
            #pragma unroll
            for (int nf = 0; nf < 8; nf++)
                mma8(d[mf][nf], a[mf], b[nf]);
    }

    const float* bnA = &g_bnA[layer * C];
    const float* bnB = &g_bnB[layer * C];
    #pragma unroll
    for (int mf = 0; mf < 2; mf++) {
        #pragma unroll
        for (int half = 0; half < 2; half++) {
            int m = m0 + wm * 32 + mf * 16 + half * 8 + grp;
            if (m < M) {
                #pragma unroll
                for (int nf = 0; nf < 8; nf++) {
                    int ncol = wn * 64 + nf * 8 + tg * 2;
                    float2 v;
                    v.x = d[mf][nf][half * 2 + 0] * bnA[ncol]     + bnB[ncol];
                    v.y = d[mf][nf][half * 2 + 1] * bnA[ncol + 1] + bnB[ncol + 1];
                    if (HASRES) {
                        float2 rv = *reinterpret_cast<const float2*>(&H[(size_t)m * 128 + ncol]);
                        v.x += rv.x; v.y += rv.y;
                    }
                    v.x = v.x > 0.f ? v.x : 0.01f * v.x;
                    v.y = v.y > 0.f ? v.y : 0.01f * v.y;
                    *reinterpret_cast<float2*>(&out[(size_t)m * 128 + ncol]) = v;
                }
            }
        }
    }
}

// ---------------- fused tail: layer-2 GEMM+BN+res+lrelu -> lin1+lrelu -> lin2 -> out ----------------
__global__ __launch_bounds__(256) void tail_kernel(const float* __restrict__ H,
                                                   const float* __restrict__ WcT,
                                                   const float* __restrict__ WT1,
                                                   const float* __restrict__ bias1,
                                                   const float* __restrict__ WT2,
                                                   const float* __restrict__ bias2,
                                                   float* __restrict__ out, int M) {
    extern __shared__ float sm[];
    float* As = sm;
    float* Ws = sm + 128 * APITCH;

    int tid = threadIdx.x;
    int wid = tid >> 5, lane = tid & 31;
    int m0 = blockIdx.x * 128;

    {
        int z = blockIdx.x * 256 + tid;
        if (z < NN) { g_deg[z] = 0.0f; g_cnt[z] = 0; }
        if (z < NSCB) g_bflag[z] = 0;
    }

    int wm = wid & 3, wn = wid >> 2;
    int grp = lane >> 2, tg = lane & 3;
    int arow = wm * 32 + grp;

    #pragma unroll
    for (int it = 0; it < 16; it++) {
        int idx = tid + it * 256;
        int r = idx >> 5, q = idx & 31;
        int m = m0 + r;
        float4 v = make_float4(0.f, 0.f, 0.f, 0.f);
        if (m < M) v = *reinterpret_cast<const float4*>(&g_agg[(size_t)m * 128 + q * 4]);
        float* p = &As[r * APITCH + q * 4];
        p[0] = to_tf32(v.x); p[1] = to_tf32(v.y); p[2] = to_tf32(v.z); p[3] = to_tf32(v.w);
    }
    #pragma unroll
    for (int it = 0; it < 16; it++) {
        int idx = tid + it * 256;
        int r = idx >> 5, q = idx & 31;
        float4 v = *reinterpret_cast<const float4*>(&WcT[(size_t)r * 128 + q * 4]);
        *reinterpret_cast<float4*>(&Ws[r * APITCH + q * 4]) = v;
    }
    __syncthreads();

    float d[2][8][4];

    // ---- stage 0: layer-2 GEMM ----
    {
        int brow = wn * 64 + grp;
        #pragma unroll
        for (int i = 0; i < 2; i++)
            #pragma unroll
            for (int j = 0; j < 8; j++)
                #pragma unroll
                for (int q = 0; q < 4; q++) d[i][j][q] = 0.0f;
        #pragma unroll
        for (int k0 = 0; k0 < 16; k0++) {
            int kk = k0 * 8 + tg;
            uint32_t a[2][4];
            #pragma unroll
            for (int mf = 0; mf < 2; mf++) {
                const float* ap = &As[(arow + mf * 16) * APITCH + kk];
                a[mf][0] = __float_as_uint(ap[0]);
                a[mf][2] = __float_as_uint(ap[4]);
                a[mf][1] = __float_as_uint(ap[8 * APITCH]);
                a[mf][3] = __float_as_uint(ap[8 * APITCH + 4]);
            }
            uint32_t b[8][2];
            #pragma unroll
            for (int nf = 0; nf < 8; nf++) {
                const float* bp = &Ws[(brow + nf * 8) * APITCH + kk];
                b[nf][0] = __float_as_uint(bp[0]);
                b[nf][1] = __float_as_uint(bp[4]);
            }
            #pragma unroll
            for (int mf = 0; mf < 2; mf++)
                #pragma unroll
                for (int nf = 0; nf < 8; nf++)
                    mma8(d[mf][nf], a[mf], b[nf]);
        }
    }
    __syncthreads();

    // z0 = lrelu(bn2(d) + residual) -> As ; stage Ws = lin1
    {
        const float* bnA = &g_bnA[2 * C];
        const float* bnB = &g_bnB[2 * C];
        #pragma unroll
        for (int mf = 0; mf < 2; mf++) {
            #pragma unroll
            for (int half = 0; half < 2; half++) {
                int r = wm * 32 + mf * 16 + half * 8 + grp;
                int m = m0 + r;
                #pragma unroll
                for (int nf = 0; nf < 8; nf++) {
                    int ncol = wn * 64 + nf * 8 + tg * 2;
                    float vx = d[mf][nf][half * 2 + 0] * bnA[ncol]     + bnB[ncol];
                    float vy = d[mf][nf][half * 2 + 1] * bnA[ncol + 1] + bnB[ncol + 1];
                    if (m < M) {
                        float2 rv = *reinterpret_cast<const float2*>(&H[(size_t)m * 128 + ncol]);
                        vx += rv.x; vy += rv.y;
                    }
                    vx = vx > 0.f ? vx : 0.01f * vx;
                    vy = vy > 0.f ? vy : 0.01f * vy;
                    As[r * APITCH + ncol]     = to_tf32(vx);
                    As[r * APITCH + ncol + 1] = to_tf32(vy);
                }
            }
        }
        #pragma unroll
        for (int it = 0; it < 16; it++) {
            int idx = tid + it * 256;
            int r = idx >> 5, q = idx & 31;
            float4 v = *reinterpret_cast<const float4*>(&WT1[(size_t)r * 128 + q * 4]);
            *reinterpret_cast<float4*>(&Ws[r * APITCH + q * 4]) = v;
        }
    }
    __syncthreads();

    // ---- stage 1: lin1 ----
    {
        int brow = wn * 64 + grp;
        #pragma unroll
        for (int i = 0; i < 2; i++)
            #pragma unroll
            for (int j = 0; j < 8; j++)
                #pragma unroll
                for (int q = 0; q < 4; q++) d[i][j][q] = 0.0f;
        #pragma unroll
        for (int k0 = 0; k0 < 16; k0++) {
            int kk = k0 * 8 + tg;
            uint32_t a[2][4];
            #pragma unroll
            for (int mf = 0; mf < 2; mf++) {
                const float* ap = &As[(arow + mf * 16) * APITCH + kk];
                a[mf][0] = __float_as_uint(ap[0]);
                a[mf][2] = __float_as_uint(ap[4]);
                a[mf][1] = __float_as_uint(ap[8 * APITCH]);
                a[mf][3] = __float_as_uint(ap[8 * APITCH + 4]);
            }
            uint32_t b[8][2];
            #pragma unroll
            for (int nf = 0; nf < 8; nf++) {
                const float* bp = &Ws[(brow + nf * 8) * APITCH + kk];
                b[nf][0] = __float_as_uint(bp[0]);
                b[nf][1] = __float_as_uint(bp[4]);
            }
            #pragma unroll
            for (int mf = 0; mf < 2; mf++)
                #pragma unroll
                for (int nf = 0; nf < 8; nf++)
                    mma8(d[mf][nf], a[mf], b[nf]);
        }
    }
    __syncthreads();

    // z1 = lrelu(d + bias1) -> As ; stage Ws = lin2
    {
        #pragma unroll
        for (int mf = 0; mf < 2; mf++) {
            #pragma unroll
            for (int half = 0; half < 2; half++) {
                int r = wm * 32 + mf * 16 + half * 8 + grp;
                #pragma unroll
                for (int nf = 0; nf < 8; nf++) {
                    int ncol = wn * 64 + nf * 8 + tg * 2;
                    float vx = d[mf][nf][half * 2 + 0] + bias1[ncol];
                    float vy = d[mf][nf][half * 2 + 1] + bias1[ncol + 1];
                    vx = vx > 0.f ? vx : 0.01f * vx;
                    vy = vy > 0.f ? vy : 0.01f * vy;
                    As[r * APITCH + ncol]     = to_tf32(vx);
                    As[r * APITCH + ncol + 1] = to_tf32(vy);
                }
            }
        }
        #pragma unroll
        for (int it = 0; it < 8; it++) {
            int idx = tid + it * 256;
            int r = idx >> 5, q = idx & 31;
            float4 v = *reinterpret_cast<const float4*>(&WT2[(size_t)r * 128 + q * 4]);
            *reinterpret_cast<float4*>(&Ws[r * APITCH + q * 4]) = v;
        }
    }
    __syncthreads();

    // ---- stage 2: lin2 -> gmem ----
    {
        int brow = wn * 32 + grp;
        float d2[2][4][4];
        #pragma unroll
        for (int i = 0; i < 2; i++)
            #pragma unroll
            for (int j = 0; j < 4; j++)
                #pragma unroll
                for (int q = 0; q < 4; q++) d2[i][j][q] = 0.0f;
        #pragma unroll
        for (int k0 = 0; k0 < 16; k0++) {
            int kk = k0 * 8 + tg;
            uint32_t a[2][4];
            #pragma unroll
            for (int mf = 0; mf < 2; mf++) {
                const float* ap = &As[(arow + mf * 16) * APITCH + kk];
                a[mf][0] = __float_as_uint(ap[0]);
                a[mf][2] = __float_as_uint(ap[4]);
                a[mf][1] = __float_as_uint(ap[8 * APITCH]);
                a[mf][3] = __float_as_uint(ap[8 * APITCH + 4]);
            }
            uint32_t b[4][2];
            #pragma unroll
            for (int nf = 0; nf < 4; nf++) {
                const float* bp = &Ws[(brow + nf * 8) * APITCH + kk];
                b[nf][0] = __float_as_uint(bp[0]);
                b[nf][1] = __float_as_uint(bp[4]);
            }
            #pragma unroll
            for (int mf = 0; mf < 2; mf++)
                #pragma unroll
                for (int nf = 0; nf < 4; nf++)
                    mma8(d2[mf][nf], a[mf], b[nf]);
        }

        #pragma unroll
        for (int mf = 0; mf < 2; mf++) {
            #pragma unroll
            for (int half = 0; half < 2; half++) {
                int m = m0 + wm * 32 + mf * 16 + half * 8 + grp;
                if (m < M) {
                    #pragma unroll
                    for (int nf = 0; nf < 4; nf++) {
                        int ncol = wn * 32 + nf * 8 + tg * 2;
                        float2 v;
                        v.x = d2[mf][nf][half * 2 + 0] + bias2[ncol];
                        v.y = d2[mf][nf][half * 2 + 1] + bias2[ncol + 1];
                        *reinterpret_cast<float2*>(&out[(size_t)m * COUT + ncol]) = v;
                    }
                }
            }
        }
    }
}

// ---------------- launch ----------------
extern "C" void kernel_launch(void* const* d_in, const int* in_sizes, int n_in,
                              void* d_out, int out_size) {
    const float* x       = (const float*)d_in[0];
    const int*   ei      = (const int*)d_in[1];
    const float* ew      = (const float*)d_in[2];
    const float* w1      = (const float*)d_in[3];
    const float* b1      = (const float*)d_in[4];
    const float* bn1_g   = (const float*)d_in[5];
    const float* bn1_b   = (const float*)d_in[6];
    const float* bn1_m   = (const float*)d_in[7];
    const float* bn1_v   = (const float*)d_in[8];
    const float* conv_ws = (const float*)d_in[9];
    const float* conv_bs = (const float*)d_in[10];
    const float* bns_g   = (const float*)d_in[11];
    const float* bns_b   = (const float*)d_in[12];
    const float* bns_m   = (const float*)d_in[13];
    const float* bns_v   = (const float*)d_in[14];
    const float* lin1_w  = (const float*)d_in[15];
    const float* lin1_b  = (const float*)d_in[16];
    const float* lin2_w  = (const float*)d_in[17];
    const float* lin2_b  = (const float*)d_in[18];

    int n = in_sizes[0] / C;     // 50000
    int e = in_sizes[2];         // 800000
    const int* srcp = ei;
    const int* dstp = ei + e;

    const int SMEM_GEMM = 256 * APITCH * 4;   // 135168

    cudaFuncSetAttribute(gemm_plain_kernel, cudaFuncAttributeMaxDynamicSharedMemorySize, SMEM_GEMM);
    cudaFuncSetAttribute(gemm_bn_kernel<1>, cudaFuncAttributeMaxDynamicSharedMemorySize, SMEM_GEMM);
    cudaFuncSetAttribute(tail_kernel,       cudaFuncAttributeMaxDynamicSharedMemorySize, SMEM_GEMM);

    float* wt = nullptr;   cudaGetSymbolAddress((void**)&wt, g_wt);
    float* bufA = nullptr; cudaGetSymbolAddress((void**)&bufA, g_bufA);
    float* bufB = nullptr; cudaGetSymbolAddress((void**)&bufB, g_bufB);

    // side stream + fork/join events (created on first call = uncaptured run)
    static cudaStream_t sB = nullptr;
    static cudaEvent_t evFork = nullptr, evScan = nullptr, evJoin = nullptr;
    if (!sB) {
        cudaStreamCreateWithFlags(&sB, cudaStreamNonBlocking);
        cudaEventCreateWithFlags(&evFork, cudaEventDisableTiming);
        cudaEventCreateWithFlags(&evScan, cudaEventDisableTiming);
        cudaEventCreateWithFlags(&evJoin, cudaEventDisableTiming);
    }

    int nb_e = (e + 255) / 256;
    int ablocks = (n + 7) / 8;
    int gblocks = (n + 127) / 128;
    int eh = (e / 2 + 255) & ~255;            // half split, aligned

    // fork
    cudaEventRecord(evFork, 0);
    cudaStreamWaitEvent(sB, evFork, 0);

    // stream A: count (+rank) -> scan -> fill first half
    count_kernel<<<nb_e, 256>>>(dstp, ew, e);
    scan_kernel<<<NSCB, SCAN_B>>>(n, b1, bn1_g, bn1_b, bn1_m, bn1_v,
                                  conv_bs, bns_g, bns_b, bns_m, bns_v);
    cudaEventRecord(evScan, 0);
    fill_kernel<<<(eh + 255) / 256, 256>>>(srcp, dstp, ew, 0, eh);

    // stream B: weight transpose -> layer-0 GEMM -> fill second half (after scan)
    tr_kernel<<<(5 * 16384 - 8192 + 255) / 256, 256, 0, sB>>>(w1, conv_ws, lin1_w, lin2_w);
    gemm_plain_kernel<<<gblocks, 256, SMEM_GEMM, sB>>>(x, wt + 0 * 16384, n);
    cudaStreamWaitEvent(sB, evScan, 0);
    fill_kernel<<<(e - eh + 255) / 256, 256, 0, sB>>>(srcp, dstp, ew, eh, e);

    // join
    cudaEventRecord(evJoin, sB);
    cudaStreamWaitEvent(0, evJoin, 0);

    // layer 0: bufA = lrelu(bn0(agg(tmp)))
    agg_bn_kernel<<<ablocks, 256>>>(n);

    // layer 1
    agg_kernel<<<ablocks, 256>>>(bufA, n);
    gemm_bn_kernel<1><<<gblocks, 256, SMEM_GEMM>>>(wt + 1 * 16384, 1, bufA, bufB, n);

    // layer 2 + heads fused (also restores zero invariants)
    agg_kernel<<<ablocks, 256>>>(bufB, n);
    tail_kernel<<<gblocks, 256, SMEM_GEMM>>>(bufB, wt + 2 * 16384, wt + 3 * 16384, lin1_b,
                                             wt + 4 * 16384, lin2_b, (float*)d_out, n);
}